// round 1
// baseline (speedup 1.0000x reference)
#include <cuda_runtime.h>
#include <cstdint>

// ---------------- problem constants ----------------
#define BB    32
#define NN    512
#define CC    512
#define HH    8
#define DHD   64
#define ADIM  8
#define MLPD  4096
#define MROWS (BB*NN)          // 16384
#define SCALE 0.125f           // 64^-0.5

// ---------------- static device scratch (no allocations allowed) ----------------
__device__ float g_x  [(size_t)MROWS*CC];     // running residual
__device__ float g_h  [(size_t)MROWS*CC];     // LN output
__device__ float g_qkv[(size_t)MROWS*3*CC];   // qkv
__device__ float g_s  [(size_t)BB*HH*NN*NN];  // attention scores
__device__ float g_ao [(size_t)MROWS*CC];     // attention output (B,N,H*DH)
__device__ float g_p1 [(size_t)MROWS*CC];     // proj / ffn output
__device__ float g_mlp[(size_t)MROWS*MLPD];   // ffn hidden
__device__ float g_d  [(size_t)MROWS*ADIM];   // adapter down (post qgelu)
__device__ float g_c  [(size_t)MROWS*ADIM];   // adapter conv (pre qgelu)

// ---------------- helpers ----------------
__device__ __forceinline__ float qgelu(float v) {
    return v / (1.0f + __expf(-1.702f * v));
}
__device__ __forceinline__ float gelu_exact(float v) {
    return 0.5f * v * (1.0f + erff(v * 0.70710678118654752f));
}

__device__ __forceinline__ float blockReduceSum256(float v) {
    __shared__ float sh[8];
    int lane = threadIdx.x & 31, w = threadIdx.x >> 5;
    #pragma unroll
    for (int o = 16; o > 0; o >>= 1) v += __shfl_down_sync(0xffffffffu, v, o);
    if (lane == 0) sh[w] = v;
    __syncthreads();
    if (threadIdx.x < 8) {
        float t = sh[threadIdx.x];
        t += __shfl_down_sync(0xffu, t, 4);
        t += __shfl_down_sync(0xffu, t, 2);
        t += __shfl_down_sync(0xffu, t, 1);
        if (threadIdx.x == 0) sh[0] = t;
    }
    __syncthreads();
    float r = sh[0];
    __syncthreads();
    return r;
}

__device__ __forceinline__ float blockReduceMax256(float v) {
    __shared__ float sh[8];
    int lane = threadIdx.x & 31, w = threadIdx.x >> 5;
    #pragma unroll
    for (int o = 16; o > 0; o >>= 1) v = fmaxf(v, __shfl_down_sync(0xffffffffu, v, o));
    if (lane == 0) sh[w] = v;
    __syncthreads();
    if (threadIdx.x < 8) {
        float t = sh[threadIdx.x];
        t = fmaxf(t, __shfl_down_sync(0xffu, t, 4));
        t = fmaxf(t, __shfl_down_sync(0xffu, t, 2));
        t = fmaxf(t, __shfl_down_sync(0xffu, t, 1));
        if (threadIdx.x == 0) sh[0] = t;
    }
    __syncthreads();
    float r = sh[0];
    __syncthreads();
    return r;
}

// ---------------- elementwise add (x + pos) ----------------
__global__ void add_kernel(const float4* __restrict__ a, const float4* __restrict__ b,
                           float4* __restrict__ o, int n4) {
    int i = blockIdx.x * 256 + threadIdx.x;
    if (i < n4) {
        float4 x = a[i], y = b[i];
        o[i] = make_float4(x.x + y.x, x.y + y.y, x.z + y.z, x.w + y.w);
    }
}

// ---------------- layernorm over last dim (C=512), one block per row ----------------
__global__ __launch_bounds__(256) void ln512(const float* __restrict__ in,
                                             const float* __restrict__ g,
                                             const float* __restrict__ b,
                                             float* __restrict__ out) {
    size_t row = blockIdx.x;
    const float* p = in + row * CC;
    int tid = threadIdx.x;
    float v0 = p[tid], v1 = p[tid + 256];
    float mean = blockReduceSum256(v0 + v1) * (1.0f / 512.0f);
    float d0 = v0 - mean, d1 = v1 - mean;
    float var = blockReduceSum256(d0 * d0 + d1 * d1) * (1.0f / 512.0f);
    float inv = rsqrtf(var + 1e-5f);
    out[row * CC + tid]       = d0 * inv * g[tid]       + b[tid];
    out[row * CC + tid + 256] = d1 * inv * g[tid + 256] + b[tid + 256];
}

// ---------------- SGEMM: C = A[MxK] * B[KxN] (+bias, +activation) ----------------
// BM=BN=128, BK=8, 256 threads, 8x8 micro-tile. M,N % 128 == 0, K % 8 == 0.
// EPI: 0 none, 1 +bias, 2 +bias +exact gelu, 3 +bias +qgelu
template<int EPI>
__global__ __launch_bounds__(256) void sgemm128(const float* __restrict__ A,
                                                const float* __restrict__ B,
                                                const float* __restrict__ bias,
                                                float* __restrict__ C,
                                                int M, int N, int K) {
    __shared__ float As[8][128];
    __shared__ float Bs[8][128];
    const int tid  = threadIdx.x;
    const int cRow = blockIdx.y * 128;
    const int cCol = blockIdx.x * 128;

    const int aRow = tid >> 1;
    const int aCol = (tid & 1) << 2;
    const int bRow = tid >> 5;
    const int bCol = (tid & 31) << 2;

    const float* Aptr = A + (size_t)(cRow + aRow) * K + aCol;
    const float* Bptr = B + (size_t)bRow * N + cCol + bCol;

    const int ty = tid >> 4, tx = tid & 15;
    float acc[8][8] = {};

    for (int k0 = 0; k0 < K; k0 += 8) {
        float4 av = *reinterpret_cast<const float4*>(Aptr);
        As[aCol + 0][aRow] = av.x;
        As[aCol + 1][aRow] = av.y;
        As[aCol + 2][aRow] = av.z;
        As[aCol + 3][aRow] = av.w;
        float4 bv = *reinterpret_cast<const float4*>(Bptr);
        *reinterpret_cast<float4*>(&Bs[bRow][bCol]) = bv;
        __syncthreads();
        Aptr += 8;
        Bptr += (size_t)8 * N;
        #pragma unroll
        for (int k = 0; k < 8; ++k) {
            float4 a0 = *reinterpret_cast<const float4*>(&As[k][ty * 8]);
            float4 a1 = *reinterpret_cast<const float4*>(&As[k][ty * 8 + 4]);
            float4 b0 = *reinterpret_cast<const float4*>(&Bs[k][tx * 8]);
            float4 b1 = *reinterpret_cast<const float4*>(&Bs[k][tx * 8 + 4]);
            float ra[8] = {a0.x, a0.y, a0.z, a0.w, a1.x, a1.y, a1.z, a1.w};
            float rb[8] = {b0.x, b0.y, b0.z, b0.w, b1.x, b1.y, b1.z, b1.w};
            #pragma unroll
            for (int i = 0; i < 8; ++i)
                #pragma unroll
                for (int j = 0; j < 8; ++j)
                    acc[i][j] += ra[i] * rb[j];
        }
        __syncthreads();
    }

    #pragma unroll
    for (int i = 0; i < 8; ++i) {
        size_t row = cRow + ty * 8 + i;
        #pragma unroll
        for (int j = 0; j < 8; j += 4) {
            int col = cCol + tx * 8 + j;
            float vals[4];
            #pragma unroll
            for (int t = 0; t < 4; ++t) {
                float val = acc[i][j + t];
                if (EPI >= 1) val += bias[col + t];
                if (EPI == 2) val = gelu_exact(val);
                else if (EPI == 3) val = qgelu(val);
                vals[t] = val;
            }
            float4 v = make_float4(vals[0], vals[1], vals[2], vals[3]);
            *reinterpret_cast<float4*>(&C[row * N + col]) = v;
        }
    }
}

// ---------------- attention: scores S = Q K^T * scale, per (b,h) ----------------
// grid: (m_tiles=8, n_tiles=8, B*H=256), 256 threads, 64x64 tile, full K=64.
__global__ __launch_bounds__(256) void attn_scores(const float* __restrict__ qkv,
                                                   float* __restrict__ S) {
    int bh = blockIdx.z;
    int b = bh >> 3, h = bh & 7;
    int ntile = blockIdx.y * 64;
    int mtile = blockIdx.x * 64;
    __shared__ float Qs[64][65];
    __shared__ float Ks[64][65];
    int tid = threadIdx.x;
    #pragma unroll
    for (int i = 0; i < 4; ++i) {
        int lin = tid + 256 * i;              // 0..1023 float4 units
        int r = lin >> 4, c4 = (lin & 15) << 2;
        float4 q = *reinterpret_cast<const float4*>(
            qkv + (size_t)(b * NN + ntile + r) * 1536 + h * 64 + c4);
        Qs[r][c4] = q.x; Qs[r][c4 + 1] = q.y; Qs[r][c4 + 2] = q.z; Qs[r][c4 + 3] = q.w;
        float4 k = *reinterpret_cast<const float4*>(
            qkv + (size_t)(b * NN + mtile + r) * 1536 + 512 + h * 64 + c4);
        Ks[r][c4] = k.x; Ks[r][c4 + 1] = k.y; Ks[r][c4 + 2] = k.z; Ks[r][c4 + 3] = k.w;
    }
    __syncthreads();
    int ty = tid >> 4, tx = tid & 15;
    float acc[4][4] = {};
    #pragma unroll 8
    for (int d = 0; d < 64; ++d) {
        float rq[4], rk[4];
        #pragma unroll
        for (int i = 0; i < 4; ++i) rq[i] = Qs[ty * 4 + i][d];
        #pragma unroll
        for (int j = 0; j < 4; ++j) rk[j] = Ks[tx * 4 + j][d];
        #pragma unroll
        for (int i = 0; i < 4; ++i)
            #pragma unroll
            for (int j = 0; j < 4; ++j)
                acc[i][j] += rq[i] * rk[j];
    }
    #pragma unroll
    for (int i = 0; i < 4; ++i)
        #pragma unroll
        for (int j = 0; j < 4; ++j)
            S[((size_t)bh * NN + ntile + ty * 4 + i) * NN + mtile + tx * 4 + j] =
                acc[i][j] * SCALE;
}

// ---------------- softmax over last axis (rows of 512), in place ----------------
__global__ __launch_bounds__(256) void softmax512(float* __restrict__ S) {
    size_t row = blockIdx.x;
    float* p = S + row * 512;
    int tid = threadIdx.x;
    float v0 = p[tid], v1 = p[tid + 256];
    float m = blockReduceMax256(fmaxf(v0, v1));
    float e0 = __expf(v0 - m), e1 = __expf(v1 - m);
    float s = blockReduceSum256(e0 + e1);
    float inv = 1.0f / s;
    p[tid] = e0 * inv;
    p[tid + 256] = e1 * inv;
}

// ---------------- attention: O = S @ V per (b,h) ----------------
// grid: (n_tiles=8, B*H=256). BM=64 (n), BN=64 (=DH), BK=32 (m).
__global__ __launch_bounds__(256) void attn_av(const float* __restrict__ S,
                                               const float* __restrict__ qkv,
                                               float* __restrict__ O) {
    int bh = blockIdx.y;
    int b = bh >> 3, h = bh & 7;
    int ntile = blockIdx.x * 64;
    __shared__ float Ss[32][65];   // [m][n]
    __shared__ float Vs[32][64];   // [m][d]
    int tid = threadIdx.x, ty = tid >> 4, tx = tid & 15;
    float acc[4][4] = {};

    for (int m0 = 0; m0 < NN; m0 += 32) {
        #pragma unroll
        for (int i = 0; i < 2; ++i) {
            int lin = tid + 256 * i;              // 0..511
            int r = lin >> 3, c4 = (lin & 7) << 2; // r: n-local, c4: m-local
            float4 v = *reinterpret_cast<const float4*>(
                S + ((size_t)bh * NN + ntile + r) * NN + m0 + c4);
            Ss[c4][r] = v.x; Ss[c4 + 1][r] = v.y; Ss[c4 + 2][r] = v.z; Ss[c4 + 3][r] = v.w;
        }
        #pragma unroll
        for (int i = 0; i < 2; ++i) {
            int lin = tid + 256 * i;
            int r = lin >> 4, c4 = (lin & 15) << 2; // r: m-local, c4: d
            float4 v = *reinterpret_cast<const float4*>(
                qkv + (size_t)(b * NN + m0 + r) * 1536 + 1024 + h * 64 + c4);
            *reinterpret_cast<float4*>(&Vs[r][c4]) = v;
        }
        __syncthreads();
        #pragma unroll
        for (int m = 0; m < 32; ++m) {
            float rs[4], rv[4];
            #pragma unroll
            for (int i = 0; i < 4; ++i) rs[i] = Ss[m][ty * 4 + i];
            #pragma unroll
            for (int j = 0; j < 4; ++j) rv[j] = Vs[m][tx * 4 + j];
            #pragma unroll
            for (int i = 0; i < 4; ++i)
                #pragma unroll
                for (int j = 0; j < 4; ++j)
                    acc[i][j] += rs[i] * rv[j];
        }
        __syncthreads();
    }
    #pragma unroll
    for (int i = 0; i < 4; ++i)
        #pragma unroll
        for (int j = 0; j < 4; ++j)
            O[(size_t)(b * NN + ntile + ty * 4 + i) * CC + h * 64 + tx * 4 + j] = acc[i][j];
}

// ---------------- adapter down: out = qgelu(h @ dw + db), [16384 x 8] ----------------
__global__ __launch_bounds__(256) void down_kernel(const float* __restrict__ h,
                                                   const float* __restrict__ dw,
                                                   const float* __restrict__ db,
                                                   float* __restrict__ out) {
    __shared__ float wsh[512 * 8];
    for (int i = threadIdx.x; i < 4096; i += 256) wsh[i] = dw[i];
    __syncthreads();
    int warp = threadIdx.x >> 5, lane = threadIdx.x & 31;
    int row = blockIdx.x * 8 + warp;
    const float* hp = h + (size_t)row * CC;
    float acc[8] = {};
    for (int k = lane; k < 512; k += 32) {
        float xv = hp[k];
        #pragma unroll
        for (int a = 0; a < 8; ++a) acc[a] += xv * wsh[k * 8 + a];
    }
    #pragma unroll
    for (int a = 0; a < 8; ++a) {
        #pragma unroll
        for (int o = 16; o > 0; o >>= 1)
            acc[a] += __shfl_down_sync(0xffffffffu, acc[a], o);
    }
    if (lane == 0) {
        #pragma unroll
        for (int a = 0; a < 8; ++a) {
            float v = acc[a] + db[a];
            out[(size_t)row * 8 + a] = qgelu(v);
        }
    }
}

// ---------------- tiny 3D conv (SAME, 3x3x3, 8->8 ch) on (B,8,8,8,A) ----------------
__global__ __launch_bounds__(256) void conv3d_kernel(const float* __restrict__ din,
                                                     const float* __restrict__ cw,
                                                     const float* __restrict__ cb,
                                                     float* __restrict__ out) {
    __shared__ float w[1728];
    __shared__ float bsh[8];
    for (int i = threadIdx.x; i < 1728; i += 256) w[i] = cw[i];
    if (threadIdx.x < 8) bsh[threadIdx.x] = cb[threadIdx.x];
    __syncthreads();
    int gid = blockIdx.x * 256 + threadIdx.x;  // B*512*8 = 131072
    int o  = gid & 7;
    int sp = (gid >> 3) & 511;
    int b  = gid >> 12;
    int xx = sp & 7, yy = (sp >> 3) & 7, zz = sp >> 6;
    float acc = bsh[o];
    for (int dz = -1; dz <= 1; ++dz) {
        int z = zz + dz; if ((unsigned)z > 7u) continue;
        for (int dy = -1; dy <= 1; ++dy) {
            int y = yy + dy; if ((unsigned)y > 7u) continue;
            for (int dx = -1; dx <= 1; ++dx) {
                int xc = xx + dx; if ((unsigned)xc > 7u) continue;
                const float* ip = din + ((size_t)b * 512 + z * 64 + y * 8 + xc) * 8;
                const float* wp = w + o * 216 + ((dz + 1) * 3 + (dy + 1)) * 3 + (dx + 1);
                #pragma unroll
                for (int i = 0; i < 8; ++i) acc += ip[i] * wp[i * 27];
            }
        }
    }
    out[gid] = acc;   // pre-activation; qgelu applied in up_combine
}

// ---------------- adapter up + residual combine ----------------
// out[n,:] = res[n,:] + add1[n,:] + (qgelu(cpre[n,:]) @ uw + ub)
__global__ __launch_bounds__(256) void up_combine(const float* __restrict__ cpre,
                                                  const float* __restrict__ uw,
                                                  const float* __restrict__ ub,
                                                  const float* __restrict__ res,
                                                  const float* __restrict__ add1,
                                                  float* __restrict__ out) {
    size_t n = blockIdx.x;
    __shared__ float p[8];
    int tid = threadIdx.x;
    if (tid < 8) p[tid] = qgelu(cpre[n * 8 + tid]);
    __syncthreads();
    #pragma unroll
    for (int it = 0; it < 2; ++it) {
        int c = tid + it * 256;
        float acc = ub[c];
        #pragma unroll
        for (int a = 0; a < 8; ++a) acc += p[a] * uw[a * 512 + c];
        out[n * CC + c] = res[n * CC + c] + add1[n * CC + c] + acc;
    }
}

// ---------------- launcher ----------------
static float* symaddr(const void* sym) {
    void* p = nullptr;
    cudaGetSymbolAddress(&p, sym);
    return (float*)p;
}

extern "C" void kernel_launch(void* const* d_in, const int* in_sizes, int n_in,
                              void* d_out, int out_size) {
    (void)in_sizes; (void)n_in; (void)out_size;
    const float* x         = (const float*)d_in[0];
    const float* pos       = (const float*)d_in[1];
    const float* ln1_g     = (const float*)d_in[2];
    const float* ln1_b     = (const float*)d_in[3];
    const float* qkv_w     = (const float*)d_in[4];
    const float* proj_w    = (const float*)d_in[5];
    const float* proj_b    = (const float*)d_in[6];
    const float* cp1_dw    = (const float*)d_in[7];
    const float* cp1_db    = (const float*)d_in[8];
    const float* cp1_cw    = (const float*)d_in[9];
    const float* cp1_cb    = (const float*)d_in[10];
    const float* cp1_uw    = (const float*)d_in[11];
    const float* cp1_ub    = (const float*)d_in[12];
    const float* ln2_g     = (const float*)d_in[13];
    const float* ln2_b     = (const float*)d_in[14];
    const float* ff_w1     = (const float*)d_in[15];
    const float* ff_b1     = (const float*)d_in[16];
    const float* ff_w2     = (const float*)d_in[17];
    const float* ff_b2     = (const float*)d_in[18];
    const float* cp2_dw    = (const float*)d_in[19];
    const float* cp2_db    = (const float*)d_in[20];
    const float* cp2_cw    = (const float*)d_in[21];
    const float* cp2_cb    = (const float*)d_in[22];
    const float* cp2_uw    = (const float*)d_in[23];
    const float* cp2_ub    = (const float*)d_in[24];
    float* out = (float*)d_out;

    float* bx   = symaddr(g_x);
    float* bh   = symaddr(g_h);
    float* bqkv = symaddr(g_qkv);
    float* bs   = symaddr(g_s);
    float* bao  = symaddr(g_ao);
    float* bp1  = symaddr(g_p1);
    float* bmlp = symaddr(g_mlp);
    float* bd   = symaddr(g_d);
    float* bc   = symaddr(g_c);

    const int n4 = (MROWS * CC) / 4;   // 2097152

    // x = x + pos
    add_kernel<<<(n4 + 255) / 256, 256>>>((const float4*)x, (const float4*)pos,
                                          (float4*)bx, n4);
    // h = LN1(x)
    ln512<<<MROWS, 256>>>(bx, ln1_g, ln1_b, bh);
    // qkv = h @ qkv_w
    sgemm128<0><<<dim3(12, 128), 256>>>(bh, qkv_w, nullptr, bqkv, MROWS, 3 * CC, CC);
    // attention
    attn_scores<<<dim3(8, 8, BB * HH), 256>>>(bqkv, bs);
    softmax512<<<BB * HH * NN, 256>>>(bs);
    attn_av<<<dim3(8, BB * HH), 256>>>(bs, bqkv, bao);
    // proj
    sgemm128<1><<<dim3(4, 128), 256>>>(bao, proj_w, proj_b, bp1, MROWS, CC, CC);
    // convpass 1 (from h)
    down_kernel<<<MROWS / 8, 256>>>(bh, cp1_dw, cp1_db, bd);
    conv3d_kernel<<<MROWS * ADIM / 256, 256>>>(bd, cp1_cw, cp1_cb, bc);
    // x = x + proj + up(qgelu(conv))
    up_combine<<<MROWS, 256>>>(bc, cp1_uw, cp1_ub, bx, bp1, bx);

    // h = LN2(x)
    ln512<<<MROWS, 256>>>(bx, ln2_g, ln2_b, bh);
    // ffn
    sgemm128<2><<<dim3(32, 128), 256>>>(bh, ff_w1, ff_b1, bmlp, MROWS, MLPD, CC);
    sgemm128<1><<<dim3(4, 128), 256>>>(bmlp, ff_w2, ff_b2, bp1, MROWS, CC, MLPD);
    // convpass 2 (from h)
    down_kernel<<<MROWS / 8, 256>>>(bh, cp2_dw, cp2_db, bd);
    conv3d_kernel<<<MROWS * ADIM / 256, 256>>>(bd, cp2_cw, cp2_cb, bc);
    // out = x + ffn + up(qgelu(conv))
    up_combine<<<MROWS, 256>>>(bc, cp2_uw, cp2_ub, bx, bp1, out);
}

// round 3
// speedup vs baseline: 2.4304x; 2.4304x over previous
#include <cuda_runtime.h>
#include <cstdint>

// ---------------- problem constants ----------------
#define BB    32
#define NN    512
#define CC    512
#define HH    8
#define DHD   64
#define ADIM  8
#define MLPD  4096
#define MROWS (BB*NN)          // 16384
#define SCALE 0.125f           // 64^-0.5

// ---------------- static device scratch ----------------
__device__ __align__(16) float g_x  [(size_t)MROWS*CC];
__device__ __align__(16) float g_h  [(size_t)MROWS*CC];
__device__ __align__(16) float g_qkv[(size_t)MROWS*3*CC];
__device__ __align__(16) float g_s  [(size_t)BB*HH*NN*NN];
__device__ __align__(16) float g_ao [(size_t)MROWS*CC];
__device__ __align__(16) float g_p1 [(size_t)MROWS*CC];
__device__ __align__(16) float g_mlp[(size_t)MROWS*MLPD];
__device__ __align__(16) float g_d  [(size_t)MROWS*ADIM];
__device__ __align__(16) float g_c  [(size_t)MROWS*ADIM];
// transposed (and tf32-rounded) weights [N,K]
__device__ __align__(16) float g_wqkvT[(size_t)3*CC*CC];
__device__ __align__(16) float g_wprojT[(size_t)CC*CC];
__device__ __align__(16) float g_wff1T[(size_t)MLPD*CC];
__device__ __align__(16) float g_wff2T[(size_t)CC*MLPD];

// ---------------- helpers ----------------
__device__ __forceinline__ float qgelu(float v) { return v / (1.0f + __expf(-1.702f * v)); }
__device__ __forceinline__ float gelu_exact(float v) { return 0.5f * v * (1.0f + erff(v * 0.70710678118654752f)); }
__device__ __forceinline__ float to_tf32(float x) {
    float r; asm("cvt.rna.tf32.f32 %0, %1;" : "=f"(r) : "f"(x)); return r;
}
__device__ __forceinline__ uint32_t smem_u32(const void* p) {
    uint32_t a;
    asm("{ .reg .u64 t; cvta.to.shared.u64 t, %1; cvt.u32.u64 %0, t; }" : "=r"(a) : "l"(p));
    return a;
}
__device__ __forceinline__ void cp16(uint32_t saddr, const void* g) {
    asm volatile("cp.async.cg.shared.global [%0], [%1], 16;" :: "r"(saddr), "l"(g));
}
__device__ __forceinline__ void mma_tf32(float d[4], const uint32_t a[4], const uint32_t b[2]) {
    asm volatile("mma.sync.aligned.m16n8k8.row.col.f32.tf32.tf32.f32 "
        "{%0,%1,%2,%3}, {%4,%5,%6,%7}, {%8,%9}, {%0,%1,%2,%3};"
        : "+f"(d[0]), "+f"(d[1]), "+f"(d[2]), "+f"(d[3])
        : "r"(a[0]), "r"(a[1]), "r"(a[2]), "r"(a[3]), "r"(b[0]), "r"(b[1]));
}

__device__ __forceinline__ float blockReduceSum256(float v) {
    __shared__ float sh[8];
    int lane = threadIdx.x & 31, w = threadIdx.x >> 5;
    #pragma unroll
    for (int o = 16; o > 0; o >>= 1) v += __shfl_down_sync(0xffffffffu, v, o);
    if (lane == 0) sh[w] = v;
    __syncthreads();
    if (threadIdx.x < 8) {
        float t = sh[threadIdx.x];
        t += __shfl_down_sync(0xffu, t, 4);
        t += __shfl_down_sync(0xffu, t, 2);
        t += __shfl_down_sync(0xffu, t, 1);
        if (threadIdx.x == 0) sh[0] = t;
    }
    __syncthreads();
    float r = sh[0];
    __syncthreads();
    return r;
}
__device__ __forceinline__ float blockReduceMax256(float v) {
    __shared__ float sh[8];
    int lane = threadIdx.x & 31, w = threadIdx.x >> 5;
    #pragma unroll
    for (int o = 16; o > 0; o >>= 1) v = fmaxf(v, __shfl_down_sync(0xffffffffu, v, o));
    if (lane == 0) sh[w] = v;
    __syncthreads();
    if (threadIdx.x < 8) {
        float t = sh[threadIdx.x];
        t = fmaxf(t, __shfl_down_sync(0xffu, t, 4));
        t = fmaxf(t, __shfl_down_sync(0xffu, t, 2));
        t = fmaxf(t, __shfl_down_sync(0xffu, t, 1));
        if (threadIdx.x == 0) sh[0] = t;
    }
    __syncthreads();
    float r = sh[0];
    __syncthreads();
    return r;
}

// ---------------- elementwise add ----------------
__global__ void add_kernel(const float4* __restrict__ a, const float4* __restrict__ b,
                           float4* __restrict__ o, int n4) {
    int i = blockIdx.x * 256 + threadIdx.x;
    if (i < n4) {
        float4 x = a[i], y = b[i];
        o[i] = make_float4(x.x + y.x, x.y + y.y, x.z + y.z, x.w + y.w);
    }
}

// ---------------- layernorm (C=512), output rounded to tf32 ----------------
__global__ __launch_bounds__(256) void ln512(const float* __restrict__ in,
                                             const float* __restrict__ g,
                                             const float* __restrict__ b,
                                             float* __restrict__ out) {
    size_t row = blockIdx.x;
    const float* p = in + row * CC;
    int tid = threadIdx.x;
    float v0 = p[tid], v1 = p[tid + 256];
    float mean = blockReduceSum256(v0 + v1) * (1.0f / 512.0f);
    float d0 = v0 - mean, d1 = v1 - mean;
    float var = blockReduceSum256(d0 * d0 + d1 * d1) * (1.0f / 512.0f);
    float inv = rsqrtf(var + 1e-5f);
    out[row * CC + tid]       = to_tf32(d0 * inv * g[tid]       + b[tid]);
    out[row * CC + tid + 256] = to_tf32(d1 * inv * g[tid + 256] + b[tid + 256]);
}

// ---------------- transpose (32x32 tiles) + tf32 rounding ----------------
__global__ void transpose_k(const float* __restrict__ in, float* __restrict__ out,
                            int R, int Cc) {
    __shared__ float t[32][33];
    int bx = blockIdx.x * 32, by = blockIdx.y * 32;
    #pragma unroll
    for (int i = 0; i < 32; i += 8) {
        int r = by + threadIdx.y + i, c = bx + threadIdx.x;
        t[threadIdx.y + i][threadIdx.x] = in[(size_t)r * Cc + c];
    }
    __syncthreads();
    #pragma unroll
    for (int i = 0; i < 32; i += 8) {
        int r = bx + threadIdx.y + i, c = by + threadIdx.x;
        out[(size_t)r * R + c] = to_tf32(t[threadIdx.x][threadIdx.y + i]);
    }
}

// ---------------- tf32 mma.sync GEMM: C[M,N] = A[M,K] @ BT[N,K]^T ----------------
// 128x128 tile, BK=32, cp.async double buffer, 8 warps (2M x 4N), warp tile 64x32.
// EPI: 0 none, 1 +bias, 2 +bias +gelu +tf32-round
#define SMS 36                      // smem row stride (floats): conflict-free frags
#define ABYTES (128*SMS*4)          // 18432
template<int EPI>
__global__ __launch_bounds__(256, 2) void tc_gemm(const float* __restrict__ A,
                                                  const float* __restrict__ BT,
                                                  const float* __restrict__ bias,
                                                  float* __restrict__ C,
                                                  int M, int N, int K) {
    extern __shared__ char smem[];
    const uint32_t sb = smem_u32(smem);
    const int tid = threadIdx.x;
    const int lane = tid & 31;
    const int w = tid >> 5;
    const int wm = w & 1;           // 0..1
    const int wn = w >> 1;          // 0..3
    const int g = lane >> 2;        // 0..7
    const int t = lane & 3;         // 0..3
    const int cRow = blockIdx.y * 128;
    const int cCol = blockIdx.x * 128;

    const int r_st = tid >> 3;            // 0..31 (row base for staging)
    const int c_st = (tid & 7) << 2;      // 0,4,..,28

    float acc[4][4][4] = {};

    // stage tile kt into buffer kt&1
    auto stage = [&](int kt) {
        const int k0 = kt << 5;
        const uint32_t ab = sb + (kt & 1) * ABYTES;
        const uint32_t bb = sb + 2 * ABYTES + (kt & 1) * ABYTES;
        #pragma unroll
        for (int i = 0; i < 4; ++i) {
            int r = r_st + i * 32;
            cp16(ab + (uint32_t)(r * SMS + c_st) * 4,
                 A + (size_t)(cRow + r) * K + k0 + c_st);
            cp16(bb + (uint32_t)(r * SMS + c_st) * 4,
                 BT + (size_t)(cCol + r) * K + k0 + c_st);
        }
        asm volatile("cp.async.commit_group;" ::: "memory");
    };

    const int NC = K >> 5;
    stage(0);
    for (int c = 0; c < NC; ++c) {
        if (c + 1 < NC) {
            stage(c + 1);
            asm volatile("cp.async.wait_group 1;" ::: "memory");
        } else {
            asm volatile("cp.async.wait_group 0;" ::: "memory");
        }
        __syncthreads();
        const float* As = (const float*)(smem + (c & 1) * ABYTES);
        const float* Bs = (const float*)(smem + 2 * ABYTES + (c & 1) * ABYTES);
        #pragma unroll
        for (int ks = 0; ks < 4; ++ks) {
            const int kk = ks * 8 + t;
            uint32_t af[4][4], bf[4][2];
            #pragma unroll
            for (int mf = 0; mf < 4; ++mf) {
                const float* ap = As + (wm * 64 + mf * 16 + g) * SMS + kk;
                af[mf][0] = __float_as_uint(ap[0]);
                af[mf][1] = __float_as_uint(ap[8 * SMS]);
                af[mf][2] = __float_as_uint(ap[4]);
                af[mf][3] = __float_as_uint(ap[8 * SMS + 4]);
            }
            #pragma unroll
            for (int nf = 0; nf < 4; ++nf) {
                const float* bp = Bs + (wn * 32 + nf * 8 + g) * SMS + kk;
                bf[nf][0] = __float_as_uint(bp[0]);
                bf[nf][1] = __float_as_uint(bp[4]);
            }
            #pragma unroll
            for (int mf = 0; mf < 4; ++mf)
                #pragma unroll
                for (int nf = 0; nf < 4; ++nf)
                    mma_tf32(acc[mf][nf], af[mf], bf[nf]);
        }
        __syncthreads();
    }

    // epilogue
    #pragma unroll
    for (int mf = 0; mf < 4; ++mf) {
        size_t row0 = (size_t)(cRow + wm * 64 + mf * 16 + g);
        size_t row1 = row0 + 8;
        #pragma unroll
        for (int nf = 0; nf < 4; ++nf) {
            int col = cCol + wn * 32 + nf * 8 + 2 * t;
            float v0 = acc[mf][nf][0], v1 = acc[mf][nf][1];
            float v2 = acc[mf][nf][2], v3 = acc[mf][nf][3];
            if (EPI >= 1) {
                float b0 = bias[col], b1 = bias[col + 1];
                v0 += b0; v1 += b1; v2 += b0; v3 += b1;
            }
            if (EPI == 2) {
                v0 = to_tf32(gelu_exact(v0)); v1 = to_tf32(gelu_exact(v1));
                v2 = to_tf32(gelu_exact(v2)); v3 = to_tf32(gelu_exact(v3));
            }
            *reinterpret_cast<float2*>(&C[row0 * N + col]) = make_float2(v0, v1);
            *reinterpret_cast<float2*>(&C[row1 * N + col]) = make_float2(v2, v3);
        }
    }
}

// ---------------- attention: S = Q K^T * scale ----------------
__global__ __launch_bounds__(256) void attn_scores(const float* __restrict__ qkv,
                                                   float* __restrict__ S) {
    int bh = blockIdx.z;
    int b = bh >> 3, h = bh & 7;
    int ntile = blockIdx.y * 64;
    int mtile = blockIdx.x * 64;
    __shared__ float Qs[64][65];
    __shared__ float Ks[64][65];
    int tid = threadIdx.x;
    #pragma unroll
    for (int i = 0; i < 4; ++i) {
        int lin = tid + 256 * i;
        int r = lin >> 4, c4 = (lin & 15) << 2;
        float4 q = *reinterpret_cast<const float4*>(
            qkv + (size_t)(b * NN + ntile + r) * 1536 + h * 64 + c4);
        Qs[r][c4] = q.x; Qs[r][c4 + 1] = q.y; Qs[r][c4 + 2] = q.z; Qs[r][c4 + 3] = q.w;
        float4 k = *reinterpret_cast<const float4*>(
            qkv + (size_t)(b * NN + mtile + r) * 1536 + 512 + h * 64 + c4);
        Ks[r][c4] = k.x; Ks[r][c4 + 1] = k.y; Ks[r][c4 + 2] = k.z; Ks[r][c4 + 3] = k.w;
    }
    __syncthreads();
    int ty = tid >> 4, tx = tid & 15;
    float acc[4][4] = {};
    #pragma unroll 8
    for (int d = 0; d < 64; ++d) {
        float rq[4], rk[4];
        #pragma unroll
        for (int i = 0; i < 4; ++i) rq[i] = Qs[ty * 4 + i][d];
        #pragma unroll
        for (int j = 0; j < 4; ++j) rk[j] = Ks[tx * 4 + j][d];
        #pragma unroll
        for (int i = 0; i < 4; ++i)
            #pragma unroll
            for (int j = 0; j < 4; ++j)
                acc[i][j] += rq[i] * rk[j];
    }
    #pragma unroll
    for (int i = 0; i < 4; ++i)
        #pragma unroll
        for (int j = 0; j < 4; ++j)
            S[((size_t)bh * NN + ntile + ty * 4 + i) * NN + mtile + tx * 4 + j] =
                acc[i][j] * SCALE;
}

// ---------------- softmax (rows of 512) ----------------
__global__ __launch_bounds__(256) void softmax512(float* __restrict__ S) {
    size_t row = blockIdx.x;
    float* p = S + row * 512;
    int tid = threadIdx.x;
    float v0 = p[tid], v1 = p[tid + 256];
    float m = blockReduceMax256(fmaxf(v0, v1));
    float e0 = __expf(v0 - m), e1 = __expf(v1 - m);
    float s = blockReduceSum256(e0 + e1);
    float inv = 1.0f / s;
    p[tid] = e0 * inv;
    p[tid + 256] = e1 * inv;
}

// ---------------- attention: O = S @ V (output tf32-rounded) ----------------
__global__ __launch_bounds__(256) void attn_av(const float* __restrict__ S,
                                               const float* __restrict__ qkv,
                                               float* __restrict__ O) {
    int bh = blockIdx.y;
    int b = bh >> 3, h = bh & 7;
    int ntile = blockIdx.x * 64;
    __shared__ float Ss[32][65];
    __shared__ float Vs[32][64];
    int tid = threadIdx.x, ty = tid >> 4, tx = tid & 15;
    float acc[4][4] = {};

    for (int m0 = 0; m0 < NN; m0 += 32) {
        #pragma unroll
        for (int i = 0; i < 2; ++i) {
            int lin = tid + 256 * i;
            int r = lin >> 3, c4 = (lin & 7) << 2;
            float4 v = *reinterpret_cast<const float4*>(
                S + ((size_t)bh * NN + ntile + r) * NN + m0 + c4);
            Ss[c4][r] = v.x; Ss[c4 + 1][r] = v.y; Ss[c4 + 2][r] = v.z; Ss[c4 + 3][r] = v.w;
        }
        #pragma unroll
        for (int i = 0; i < 2; ++i) {
            int lin = tid + 256 * i;
            int r = lin >> 4, c4 = (lin & 15) << 2;
            float4 v = *reinterpret_cast<const float4*>(
                qkv + (size_t)(b * NN + m0 + r) * 1536 + 1024 + h * 64 + c4);
            *reinterpret_cast<float4*>(&Vs[r][c4]) = v;
        }
        __syncthreads();
        #pragma unroll
        for (int m = 0; m < 32; ++m) {
            float rs[4], rv[4];
            #pragma unroll
            for (int i = 0; i < 4; ++i) rs[i] = Ss[m][ty * 4 + i];
            #pragma unroll
            for (int j = 0; j < 4; ++j) rv[j] = Vs[m][tx * 4 + j];
            #pragma unroll
            for (int i = 0; i < 4; ++i)
                #pragma unroll
                for (int j = 0; j < 4; ++j)
                    acc[i][j] += rs[i] * rv[j];
        }
        __syncthreads();
    }
    #pragma unroll
    for (int i = 0; i < 4; ++i)
        #pragma unroll
        for (int j = 0; j < 4; ++j)
            O[(size_t)(b * NN + ntile + ty * 4 + i) * CC + h * 64 + tx * 4 + j] =
                to_tf32(acc[i][j]);
}

// ---------------- adapter down ----------------
__global__ __launch_bounds__(256) void down_kernel(const float* __restrict__ h,
                                                   const float* __restrict__ dw,
                                                   const float* __restrict__ db,
                                                   float* __restrict__ out) {
    __shared__ float wsh[512 * 8];
    for (int i = threadIdx.x; i < 4096; i += 256) wsh[i] = dw[i];
    __syncthreads();
    int warp = threadIdx.x >> 5, lane = threadIdx.x & 31;
    int row = blockIdx.x * 8 + warp;
    const float* hp = h + (size_t)row * CC;
    float acc[8] = {};
    for (int k = lane; k < 512; k += 32) {
        float xv = hp[k];
        #pragma unroll
        for (int a = 0; a < 8; ++a) acc[a] += xv * wsh[k * 8 + a];
    }
    #pragma unroll
    for (int a = 0; a < 8; ++a) {
        #pragma unroll
        for (int o = 16; o > 0; o >>= 1)
            acc[a] += __shfl_down_sync(0xffffffffu, acc[a], o);
    }
    if (lane == 0) {
        #pragma unroll
        for (int a = 0; a < 8; ++a)
            out[(size_t)row * 8 + a] = qgelu(acc[a] + db[a]);
    }
}

// ---------------- tiny 3D conv ----------------
__global__ __launch_bounds__(256) void conv3d_kernel(const float* __restrict__ din,
                                                     const float* __restrict__ cw,
                                                     const float* __restrict__ cb,
                                                     float* __restrict__ out) {
    __shared__ float w[1728];
    __shared__ float bsh[8];
    for (int i = threadIdx.x; i < 1728; i += 256) w[i] = cw[i];
    if (threadIdx.x < 8) bsh[threadIdx.x] = cb[threadIdx.x];
    __syncthreads();
    int gid = blockIdx.x * 256 + threadIdx.x;
    int o  = gid & 7;
    int sp = (gid >> 3) & 511;
    int b  = gid >> 12;
    int xx = sp & 7, yy = (sp >> 3) & 7, zz = sp >> 6;
    float acc = bsh[o];
    for (int dz = -1; dz <= 1; ++dz) {
        int z = zz + dz; if ((unsigned)z > 7u) continue;
        for (int dy = -1; dy <= 1; ++dy) {
            int y = yy + dy; if ((unsigned)y > 7u) continue;
            for (int dx = -1; dx <= 1; ++dx) {
                int xc = xx + dx; if ((unsigned)xc > 7u) continue;
                const float* ip = din + ((size_t)b * 512 + z * 64 + y * 8 + xc) * 8;
                const float* wp = w + o * 216 + ((dz + 1) * 3 + (dy + 1)) * 3 + (dx + 1);
                #pragma unroll
                for (int i = 0; i < 8; ++i) acc += ip[i] * wp[i * 27];
            }
        }
    }
    out[gid] = acc;
}

// ---------------- adapter up + combine ----------------
__global__ __launch_bounds__(256) void up_combine(const float* __restrict__ cpre,
                                                  const float* __restrict__ uw,
                                                  const float* __restrict__ ub,
                                                  const float* __restrict__ res,
                                                  const float* __restrict__ add1,
                                                  float* __restrict__ out) {
    size_t n = blockIdx.x;
    __shared__ float p[8];
    int tid = threadIdx.x;
    if (tid < 8) p[tid] = qgelu(cpre[n * 8 + tid]);
    __syncthreads();
    #pragma unroll
    for (int it = 0; it < 2; ++it) {
        int c = tid + it * 256;
        float acc = ub[c];
        #pragma unroll
        for (int a = 0; a < 8; ++a) acc += p[a] * uw[a * 512 + c];
        out[n * CC + c] = res[n * CC + c] + add1[n * CC + c] + acc;
    }
}

// ---------------- launcher ----------------
static float* symaddr(const void* sym) {
    void* p = nullptr;
    cudaGetSymbolAddress(&p, sym);
    return (float*)p;
}

extern "C" void kernel_launch(void* const* d_in, const int* in_sizes, int n_in,
                              void* d_out, int out_size) {
    (void)in_sizes; (void)n_in; (void)out_size;
    const float* x      = (const float*)d_in[0];
    const float* pos    = (const float*)d_in[1];
    const float* ln1_g  = (const float*)d_in[2];
    const float* ln1_b  = (const float*)d_in[3];
    const float* qkv_w  = (const float*)d_in[4];
    const float* proj_w = (const float*)d_in[5];
    const float* proj_b = (const float*)d_in[6];
    const float* cp1_dw = (const float*)d_in[7];
    const float* cp1_db = (const float*)d_in[8];
    const float* cp1_cw = (const float*)d_in[9];
    const float* cp1_cb = (const float*)d_in[10];
    const float* cp1_uw = (const float*)d_in[11];
    const float* cp1_ub = (const float*)d_in[12];
    const float* ln2_g  = (const float*)d_in[13];
    const float* ln2_b  = (const float*)d_in[14];
    const float* ff_w1  = (const float*)d_in[15];
    const float* ff_b1  = (const float*)d_in[16];
    const float* ff_w2  = (const float*)d_in[17];
    const float* ff_b2  = (const float*)d_in[18];
    const float* cp2_dw = (const float*)d_in[19];
    const float* cp2_db = (const float*)d_in[20];
    const float* cp2_cw = (const float*)d_in[21];
    const float* cp2_cb = (const float*)d_in[22];
    const float* cp2_uw = (const float*)d_in[23];
    const float* cp2_ub = (const float*)d_in[24];
    float* out = (float*)d_out;

    float* bx    = symaddr(g_x);
    float* bh    = symaddr(g_h);
    float* bqkv  = symaddr(g_qkv);
    float* bs    = symaddr(g_s);
    float* bao   = symaddr(g_ao);
    float* bp1   = symaddr(g_p1);
    float* bmlp  = symaddr(g_mlp);
    float* bd    = symaddr(g_d);
    float* bc    = symaddr(g_c);
    float* wqkvT = symaddr(g_wqkvT);
    float* wprojT= symaddr(g_wprojT);
    float* wff1T = symaddr(g_wff1T);
    float* wff2T = symaddr(g_wff2T);

    const int GEMM_SMEM = 4 * ABYTES;  // 73728
    cudaFuncSetAttribute(tc_gemm<0>, cudaFuncAttributeMaxDynamicSharedMemorySize, GEMM_SMEM);
    cudaFuncSetAttribute(tc_gemm<1>, cudaFuncAttributeMaxDynamicSharedMemorySize, GEMM_SMEM);
    cudaFuncSetAttribute(tc_gemm<2>, cudaFuncAttributeMaxDynamicSharedMemorySize, GEMM_SMEM);

    const int n4 = (MROWS * CC) / 4;

    // weight transposes [K,N] -> [N,K] (tf32 rounded)
    transpose_k<<<dim3(1536 / 32, 512 / 32), dim3(32, 8)>>>(qkv_w, wqkvT, 512, 1536);
    transpose_k<<<dim3(512 / 32, 512 / 32), dim3(32, 8)>>>(proj_w, wprojT, 512, 512);
    transpose_k<<<dim3(4096 / 32, 512 / 32), dim3(32, 8)>>>(ff_w1, wff1T, 512, 4096);
    transpose_k<<<dim3(512 / 32, 4096 / 32), dim3(32, 8)>>>(ff_w2, wff2T, 4096, 512);

    // x = x + pos ; h = LN1(x)
    add_kernel<<<(n4 + 255) / 256, 256>>>((const float4*)x, (const float4*)pos, (float4*)bx, n4);
    ln512<<<MROWS, 256>>>(bx, ln1_g, ln1_b, bh);

    // qkv = h @ qkv_w  (tf32 mma)
    tc_gemm<0><<<dim3(12, 128), 256, GEMM_SMEM>>>(bh, wqkvT, nullptr, bqkv, MROWS, 3 * CC, CC);

    // attention
    attn_scores<<<dim3(8, 8, BB * HH), 256>>>(bqkv, bs);
    softmax512<<<BB * HH * NN, 256>>>(bs);
    attn_av<<<dim3(8, BB * HH), 256>>>(bs, bqkv, bao);

    // proj
    tc_gemm<1><<<dim3(4, 128), 256, GEMM_SMEM>>>(bao, wprojT, proj_b, bp1, MROWS, CC, CC);

    // convpass 1
    down_kernel<<<MROWS / 8, 256>>>(bh, cp1_dw, cp1_db, bd);
    conv3d_kernel<<<MROWS * ADIM / 256, 256>>>(bd, cp1_cw, cp1_cb, bc);
    up_combine<<<MROWS, 256>>>(bc, cp1_uw, cp1_ub, bx, bp1, bx);

    // h = LN2(x) ; FFN
    ln512<<<MROWS, 256>>>(bx, ln2_g, ln2_b, bh);
    tc_gemm<2><<<dim3(32, 128), 256, GEMM_SMEM>>>(bh, wff1T, ff_b1, bmlp, MROWS, MLPD, CC);
    tc_gemm<1><<<dim3(4, 128), 256, GEMM_SMEM>>>(bmlp, wff2T, ff_b2, bp1, MROWS, CC, MLPD);

    // convpass 2 + final combine
    down_kernel<<<MROWS / 8, 256>>>(bh, cp2_dw, cp2_db, bd);
    conv3d_kernel<<<MROWS * ADIM / 256, 256>>>(bd, cp2_cw, cp2_cb, bc);
    up_combine<<<MROWS, 256>>>(bc, cp2_uw, cp2_ub, bx, bp1, out);
}

// round 4
// speedup vs baseline: 3.2720x; 1.3463x over previous
#include <cuda_runtime.h>
#include <cstdint>

// ---------------- problem constants ----------------
#define BB    32
#define NN    512
#define CC    512
#define HH    8
#define DHD   64
#define ADIM  8
#define MLPD  4096
#define MROWS (BB*NN)          // 16384
#define SCALE 0.125f           // 64^-0.5

// ---------------- static device scratch ----------------
__device__ __align__(16) float g_x  [(size_t)MROWS*CC];
__device__ __align__(16) float g_h  [(size_t)MROWS*CC];
__device__ __align__(16) float g_qkv[(size_t)MROWS*3*CC];
__device__ __align__(16) float g_ao [(size_t)MROWS*CC];
__device__ __align__(16) float g_p1 [(size_t)MROWS*CC];
__device__ __align__(16) float g_mlp[(size_t)MROWS*MLPD];
__device__ __align__(16) float g_d  [(size_t)MROWS*ADIM];
__device__ __align__(16) float g_c  [(size_t)MROWS*ADIM];
// transposed (and tf32-rounded) weights [N,K]
__device__ __align__(16) float g_wqkvT[(size_t)3*CC*CC];
__device__ __align__(16) float g_wprojT[(size_t)CC*CC];
__device__ __align__(16) float g_wff1T[(size_t)MLPD*CC];
__device__ __align__(16) float g_wff2T[(size_t)CC*MLPD];

// ---------------- helpers ----------------
__device__ __forceinline__ float qgelu(float v) { return v / (1.0f + __expf(-1.702f * v)); }
__device__ __forceinline__ float gelu_exact(float v) { return 0.5f * v * (1.0f + erff(v * 0.70710678118654752f)); }
__device__ __forceinline__ float to_tf32(float x) {
    float r; asm("cvt.rna.tf32.f32 %0, %1;" : "=f"(r) : "f"(x)); return r;
}
__device__ __forceinline__ uint32_t smem_u32(const void* p) {
    uint32_t a;
    asm("{ .reg .u64 t; cvta.to.shared.u64 t, %1; cvt.u32.u64 %0, t; }" : "=r"(a) : "l"(p));
    return a;
}
__device__ __forceinline__ void cp16(uint32_t saddr, const void* g) {
    asm volatile("cp.async.cg.shared.global [%0], [%1], 16;" :: "r"(saddr), "l"(g));
}
__device__ __forceinline__ void mma_tf32(float d[4], const uint32_t a[4], const uint32_t b[2]) {
    asm volatile("mma.sync.aligned.m16n8k8.row.col.f32.tf32.tf32.f32 "
        "{%0,%1,%2,%3}, {%4,%5,%6,%7}, {%8,%9}, {%0,%1,%2,%3};"
        : "+f"(d[0]), "+f"(d[1]), "+f"(d[2]), "+f"(d[3])
        : "r"(a[0]), "r"(a[1]), "r"(a[2]), "r"(a[3]), "r"(b[0]), "r"(b[1]));
}

__device__ __forceinline__ float blockReduceSum256(float v) {
    __shared__ float sh[8];
    int lane = threadIdx.x & 31, w = threadIdx.x >> 5;
    #pragma unroll
    for (int o = 16; o > 0; o >>= 1) v += __shfl_down_sync(0xffffffffu, v, o);
    if (lane == 0) sh[w] = v;
    __syncthreads();
    if (threadIdx.x < 8) {
        float t = sh[threadIdx.x];
        t += __shfl_down_sync(0xffu, t, 4);
        t += __shfl_down_sync(0xffu, t, 2);
        t += __shfl_down_sync(0xffu, t, 1);
        if (threadIdx.x == 0) sh[0] = t;
    }
    __syncthreads();
    float r = sh[0];
    __syncthreads();
    return r;
}

// ---------------- elementwise add ----------------
__global__ void add_kernel(const float4* __restrict__ a, const float4* __restrict__ b,
                           float4* __restrict__ o, int n4) {
    int i = blockIdx.x * 256 + threadIdx.x;
    if (i < n4) {
        float4 x = a[i], y = b[i];
        o[i] = make_float4(x.x + y.x, x.y + y.y, x.z + y.z, x.w + y.w);
    }
}

// ---------------- layernorm (C=512), output rounded to tf32 ----------------
__global__ __launch_bounds__(256) void ln512(const float* __restrict__ in,
                                             const float* __restrict__ g,
                                             const float* __restrict__ b,
                                             float* __restrict__ out) {
    size_t row = blockIdx.x;
    const float* p = in + row * CC;
    int tid = threadIdx.x;
    float v0 = p[tid], v1 = p[tid + 256];
    float mean = blockReduceSum256(v0 + v1) * (1.0f / 512.0f);
    float d0 = v0 - mean, d1 = v1 - mean;
    float var = blockReduceSum256(d0 * d0 + d1 * d1) * (1.0f / 512.0f);
    float inv = rsqrtf(var + 1e-5f);
    out[row * CC + tid]       = to_tf32(d0 * inv * g[tid]       + b[tid]);
    out[row * CC + tid + 256] = to_tf32(d1 * inv * g[tid + 256] + b[tid + 256]);
}

// ---------------- transpose (32x32 tiles) + tf32 rounding ----------------
__global__ void transpose_k(const float* __restrict__ in, float* __restrict__ out,
                            int R, int Cc) {
    __shared__ float t[32][33];
    int bx = blockIdx.x * 32, by = blockIdx.y * 32;
    #pragma unroll
    for (int i = 0; i < 32; i += 8) {
        int r = by + threadIdx.y + i, c = bx + threadIdx.x;
        t[threadIdx.y + i][threadIdx.x] = in[(size_t)r * Cc + c];
    }
    __syncthreads();
    #pragma unroll
    for (int i = 0; i < 32; i += 8) {
        int r = bx + threadIdx.y + i, c = by + threadIdx.x;
        out[(size_t)r * R + c] = to_tf32(t[threadIdx.x][threadIdx.y + i]);
    }
}

// ---------------- tf32 mma.sync GEMM: C[M,N] = A[M,K] @ BT[N,K]^T ----------------
#define SMS 36
#define ABYTES (128*SMS*4)
template<int EPI>
__global__ __launch_bounds__(256, 2) void tc_gemm(const float* __restrict__ A,
                                                  const float* __restrict__ BT,
                                                  const float* __restrict__ bias,
                                                  float* __restrict__ C,
                                                  int M, int N, int K) {
    extern __shared__ char smem[];
    const uint32_t sb = smem_u32(smem);
    const int tid = threadIdx.x;
    const int lane = tid & 31;
    const int w = tid >> 5;
    const int wm = w & 1;
    const int wn = w >> 1;
    const int g = lane >> 2;
    const int t = lane & 3;
    const int cRow = blockIdx.y * 128;
    const int cCol = blockIdx.x * 128;

    const int r_st = tid >> 3;
    const int c_st = (tid & 7) << 2;

    float acc[4][4][4] = {};

    auto stage = [&](int kt) {
        const int k0 = kt << 5;
        const uint32_t ab = sb + (kt & 1) * ABYTES;
        const uint32_t bb = sb + 2 * ABYTES + (kt & 1) * ABYTES;
        #pragma unroll
        for (int i = 0; i < 4; ++i) {
            int r = r_st + i * 32;
            cp16(ab + (uint32_t)(r * SMS + c_st) * 4,
                 A + (size_t)(cRow + r) * K + k0 + c_st);
            cp16(bb + (uint32_t)(r * SMS + c_st) * 4,
                 BT + (size_t)(cCol + r) * K + k0 + c_st);
        }
        asm volatile("cp.async.commit_group;" ::: "memory");
    };

    const int NC = K >> 5;
    stage(0);
    for (int c = 0; c < NC; ++c) {
        if (c + 1 < NC) {
            stage(c + 1);
            asm volatile("cp.async.wait_group 1;" ::: "memory");
        } else {
            asm volatile("cp.async.wait_group 0;" ::: "memory");
        }
        __syncthreads();
        const float* As = (const float*)(smem + (c & 1) * ABYTES);
        const float* Bs = (const float*)(smem + 2 * ABYTES + (c & 1) * ABYTES);
        #pragma unroll
        for (int ks = 0; ks < 4; ++ks) {
            const int kk = ks * 8 + t;
            uint32_t af[4][4], bf[4][2];
            #pragma unroll
            for (int mf = 0; mf < 4; ++mf) {
                const float* ap = As + (wm * 64 + mf * 16 + g) * SMS + kk;
                af[mf][0] = __float_as_uint(ap[0]);
                af[mf][1] = __float_as_uint(ap[8 * SMS]);
                af[mf][2] = __float_as_uint(ap[4]);
                af[mf][3] = __float_as_uint(ap[8 * SMS + 4]);
            }
            #pragma unroll
            for (int nf = 0; nf < 4; ++nf) {
                const float* bp = Bs + (wn * 32 + nf * 8 + g) * SMS + kk;
                bf[nf][0] = __float_as_uint(bp[0]);
                bf[nf][1] = __float_as_uint(bp[4]);
            }
            #pragma unroll
            for (int mf = 0; mf < 4; ++mf)
                #pragma unroll
                for (int nf = 0; nf < 4; ++nf)
                    mma_tf32(acc[mf][nf], af[mf], bf[nf]);
        }
        __syncthreads();
    }

    #pragma unroll
    for (int mf = 0; mf < 4; ++mf) {
        size_t row0 = (size_t)(cRow + wm * 64 + mf * 16 + g);
        size_t row1 = row0 + 8;
        #pragma unroll
        for (int nf = 0; nf < 4; ++nf) {
            int col = cCol + wn * 32 + nf * 8 + 2 * t;
            float v0 = acc[mf][nf][0], v1 = acc[mf][nf][1];
            float v2 = acc[mf][nf][2], v3 = acc[mf][nf][3];
            if (EPI >= 1) {
                float b0 = bias[col], b1 = bias[col + 1];
                v0 += b0; v1 += b1; v2 += b0; v3 += b1;
            }
            if (EPI == 2) {
                v0 = to_tf32(gelu_exact(v0)); v1 = to_tf32(gelu_exact(v1));
                v2 = to_tf32(gelu_exact(v2)); v3 = to_tf32(gelu_exact(v3));
            }
            *reinterpret_cast<float2*>(&C[row0 * N + col]) = make_float2(v0, v1);
            *reinterpret_cast<float2*>(&C[row1 * N + col]) = make_float2(v2, v3);
        }
    }
}

// ---------------- fused flash attention (tf32 mma) ----------------
// grid (4, B*H); block 256 = 8 warps; each warp owns 16 query rows.
// smem: P[128][68] | K[64][68] | Vt[64][68]  (floats, stride 68 -> conflict-free)
#define FA_SMEM ((128*68 + 64*68 + 64*68) * 4)
__global__ __launch_bounds__(256) void flash_attn(const float* __restrict__ qkv,
                                                  float* __restrict__ O) {
    extern __shared__ float fs[];
    float* Ps = fs;               // 128*68
    float* Ks = fs + 128 * 68;    // 64*68
    float* Vt = Ks + 64 * 68;     // 64*68
    const int tid = threadIdx.x;
    const int lane = tid & 31;
    const int w = tid >> 5;
    const int g = lane >> 2, t = lane & 3;
    const int qt = blockIdx.x;
    const int bh = blockIdx.y;
    const int b = bh >> 3, h = bh & 7;
    const int r0 = w * 16 + g;

    // stage Q (scaled + tf32) into Ps
    const size_t qbase = ((size_t)b * NN + qt * 128) * 1536 + h * 64;
    #pragma unroll
    for (int i = 0; i < 8; ++i) {
        int lin = tid + 256 * i;          // 0..2047 float4 units
        int r = lin >> 4, c4 = (lin & 15) << 2;
        float4 q = *reinterpret_cast<const float4*>(qkv + qbase + (size_t)r * 1536 + c4);
        float* d = Ps + r * 68 + c4;
        d[0] = to_tf32(q.x * SCALE); d[1] = to_tf32(q.y * SCALE);
        d[2] = to_tf32(q.z * SCALE); d[3] = to_tf32(q.w * SCALE);
    }
    __syncthreads();
    uint32_t qf[8][4];
    #pragma unroll
    for (int ks = 0; ks < 8; ++ks) {
        const float* p = Ps + r0 * 68 + ks * 8 + t;
        qf[ks][0] = __float_as_uint(p[0]);
        qf[ks][1] = __float_as_uint(p[8 * 68]);
        qf[ks][2] = __float_as_uint(p[4]);
        qf[ks][3] = __float_as_uint(p[8 * 68 + 4]);
    }
    __syncthreads();   // Ps now reusable for P

    float oacc[8][4] = {};
    float m0 = -1e30f, m1 = -1e30f, l0 = 0.f, l1 = 0.f;

    const size_t kbase = (size_t)b * NN * 1536 + 512 + h * 64;
    const size_t vbase = kbase + 512;

    for (int kt = 0; kt < 8; ++kt) {
        // load K tile [key][feat] and V tile transposed [feat][key]
        #pragma unroll
        for (int i = 0; i < 4; ++i) {
            int lin = tid + 256 * i;      // 0..1023
            int r = lin >> 4, c4 = (lin & 15) << 2;
            size_t off = (size_t)(kt * 64 + r) * 1536 + c4;
            float4 kv = *reinterpret_cast<const float4*>(qkv + kbase + off);
            float* d = Ks + r * 68 + c4;
            d[0] = to_tf32(kv.x); d[1] = to_tf32(kv.y);
            d[2] = to_tf32(kv.z); d[3] = to_tf32(kv.w);
            float4 vv = *reinterpret_cast<const float4*>(qkv + vbase + off);
            Vt[(c4 + 0) * 68 + r] = to_tf32(vv.x);
            Vt[(c4 + 1) * 68 + r] = to_tf32(vv.y);
            Vt[(c4 + 2) * 68 + r] = to_tf32(vv.z);
            Vt[(c4 + 3) * 68 + r] = to_tf32(vv.w);
        }
        __syncthreads();

        // S = Q K^T  (16 q-rows x 64 keys per warp)
        float sacc[8][4] = {};
        #pragma unroll
        for (int ks = 0; ks < 8; ++ks) {
            #pragma unroll
            for (int nf = 0; nf < 8; ++nf) {
                const float* bp = Ks + (nf * 8 + g) * 68 + ks * 8 + t;
                uint32_t bf[2] = {__float_as_uint(bp[0]), __float_as_uint(bp[4])};
                mma_tf32(sacc[nf], qf[ks], bf);
            }
        }
        // online softmax
        float mx0 = -1e30f, mx1 = -1e30f;
        #pragma unroll
        for (int nf = 0; nf < 8; ++nf) {
            mx0 = fmaxf(mx0, fmaxf(sacc[nf][0], sacc[nf][1]));
            mx1 = fmaxf(mx1, fmaxf(sacc[nf][2], sacc[nf][3]));
        }
        mx0 = fmaxf(mx0, __shfl_xor_sync(0xffffffffu, mx0, 1));
        mx0 = fmaxf(mx0, __shfl_xor_sync(0xffffffffu, mx0, 2));
        mx1 = fmaxf(mx1, __shfl_xor_sync(0xffffffffu, mx1, 1));
        mx1 = fmaxf(mx1, __shfl_xor_sync(0xffffffffu, mx1, 2));
        float mn0 = fmaxf(m0, mx0), mn1 = fmaxf(m1, mx1);
        float f0 = __expf(m0 - mn0), f1 = __expf(m1 - mn1);
        m0 = mn0; m1 = mn1;
        float rs0 = 0.f, rs1 = 0.f;
        #pragma unroll
        for (int nf = 0; nf < 8; ++nf) {
            sacc[nf][0] = __expf(sacc[nf][0] - mn0);
            sacc[nf][1] = __expf(sacc[nf][1] - mn0);
            sacc[nf][2] = __expf(sacc[nf][2] - mn1);
            sacc[nf][3] = __expf(sacc[nf][3] - mn1);
            rs0 += sacc[nf][0] + sacc[nf][1];
            rs1 += sacc[nf][2] + sacc[nf][3];
        }
        rs0 += __shfl_xor_sync(0xffffffffu, rs0, 1);
        rs0 += __shfl_xor_sync(0xffffffffu, rs0, 2);
        rs1 += __shfl_xor_sync(0xffffffffu, rs1, 1);
        rs1 += __shfl_xor_sync(0xffffffffu, rs1, 2);
        l0 = l0 * f0 + rs0; l1 = l1 * f1 + rs1;
        #pragma unroll
        for (int nf = 0; nf < 8; ++nf) {
            oacc[nf][0] *= f0; oacc[nf][1] *= f0;
            oacc[nf][2] *= f1; oacc[nf][3] *= f1;
        }
        // P -> smem (each warp owns its 16 rows; warp-local round trip)
        #pragma unroll
        for (int nf = 0; nf < 8; ++nf) {
            float* pr = Ps + r0 * 68 + nf * 8 + 2 * t;
            *reinterpret_cast<float2*>(pr) =
                make_float2(to_tf32(sacc[nf][0]), to_tf32(sacc[nf][1]));
            *reinterpret_cast<float2*>(pr + 8 * 68) =
                make_float2(to_tf32(sacc[nf][2]), to_tf32(sacc[nf][3]));
        }
        __syncwarp();
        // O += P @ V
        #pragma unroll
        for (int ks = 0; ks < 8; ++ks) {
            const float* ap = Ps + r0 * 68 + ks * 8 + t;
            uint32_t af[4] = {__float_as_uint(ap[0]), __float_as_uint(ap[8 * 68]),
                              __float_as_uint(ap[4]), __float_as_uint(ap[8 * 68 + 4])};
            #pragma unroll
            for (int nf = 0; nf < 8; ++nf) {
                const float* bp = Vt + (nf * 8 + g) * 68 + ks * 8 + t;
                uint32_t bf[2] = {__float_as_uint(bp[0]), __float_as_uint(bp[4])};
                mma_tf32(oacc[nf], af, bf);
            }
        }
        __syncthreads();
    }

    float i0 = 1.0f / l0, i1 = 1.0f / l1;
    size_t orow = (size_t)(b * NN + qt * 128 + r0);
    #pragma unroll
    for (int nf = 0; nf < 8; ++nf) {
        int col = h * 64 + nf * 8 + 2 * t;
        *reinterpret_cast<float2*>(&O[orow * CC + col]) =
            make_float2(to_tf32(oacc[nf][0] * i0), to_tf32(oacc[nf][1] * i0));
        *reinterpret_cast<float2*>(&O[(orow + 8) * CC + col]) =
            make_float2(to_tf32(oacc[nf][2] * i1), to_tf32(oacc[nf][3] * i1));
    }
}

// ---------------- adapter down ----------------
__global__ __launch_bounds__(256) void down_kernel(const float* __restrict__ h,
                                                   const float* __restrict__ dw,
                                                   const float* __restrict__ db,
                                                   float* __restrict__ out) {
    __shared__ float wsh[512 * 8];
    for (int i = threadIdx.x; i < 4096; i += 256) wsh[i] = dw[i];
    __syncthreads();
    int warp = threadIdx.x >> 5, lane = threadIdx.x & 31;
    int row = blockIdx.x * 8 + warp;
    const float* hp = h + (size_t)row * CC;
    float acc[8] = {};
    for (int k = lane; k < 512; k += 32) {
        float xv = hp[k];
        #pragma unroll
        for (int a = 0; a < 8; ++a) acc[a] += xv * wsh[k * 8 + a];
    }
    #pragma unroll
    for (int a = 0; a < 8; ++a) {
        #pragma unroll
        for (int o = 16; o > 0; o >>= 1)
            acc[a] += __shfl_down_sync(0xffffffffu, acc[a], o);
    }
    if (lane == 0) {
        #pragma unroll
        for (int a = 0; a < 8; ++a)
            out[(size_t)row * 8 + a] = qgelu(acc[a] + db[a]);
    }
}

// ---------------- tiny 3D conv ----------------
__global__ __launch_bounds__(256) void conv3d_kernel(const float* __restrict__ din,
                                                     const float* __restrict__ cw,
                                                     const float* __restrict__ cb,
                                                     float* __restrict__ out) {
    __shared__ float w[1728];
    __shared__ float bsh[8];
    for (int i = threadIdx.x; i < 1728; i += 256) w[i] = cw[i];
    if (threadIdx.x < 8) bsh[threadIdx.x] = cb[threadIdx.x];
    __syncthreads();
    int gid = blockIdx.x * 256 + threadIdx.x;
    int o  = gid & 7;
    int sp = (gid >> 3) & 511;
    int b  = gid >> 12;
    int xx = sp & 7, yy = (sp >> 3) & 7, zz = sp >> 6;
    float acc = bsh[o];
    for (int dz = -1; dz <= 1; ++dz) {
        int z = zz + dz; if ((unsigned)z > 7u) continue;
        for (int dy = -1; dy <= 1; ++dy) {
            int y = yy + dy; if ((unsigned)y > 7u) continue;
            for (int dx = -1; dx <= 1; ++dx) {
                int xc = xx + dx; if ((unsigned)xc > 7u) continue;
                const float* ip = din + ((size_t)b * 512 + z * 64 + y * 8 + xc) * 8;
                const float* wp = w + o * 216 + ((dz + 1) * 3 + (dy + 1)) * 3 + (dx + 1);
                #pragma unroll
                for (int i = 0; i < 8; ++i) acc += ip[i] * wp[i * 27];
            }
        }
    }
    out[gid] = acc;
}

// ---------------- adapter up + combine ----------------
__global__ __launch_bounds__(256) void up_combine(const float* __restrict__ cpre,
                                                  const float* __restrict__ uw,
                                                  const float* __restrict__ ub,
                                                  const float* __restrict__ res,
                                                  const float* __restrict__ add1,
                                                  float* __restrict__ out) {
    size_t n = blockIdx.x;
    __shared__ float p[8];
    int tid = threadIdx.x;
    if (tid < 8) p[tid] = qgelu(cpre[n * 8 + tid]);
    __syncthreads();
    #pragma unroll
    for (int it = 0; it < 2; ++it) {
        int c = tid + it * 256;
        float acc = ub[c];
        #pragma unroll
        for (int a = 0; a < 8; ++a) acc += p[a] * uw[a * 512 + c];
        out[n * CC + c] = res[n * CC + c] + add1[n * CC + c] + acc;
    }
}

// ---------------- launcher ----------------
static float* symaddr(const void* sym) {
    void* p = nullptr;
    cudaGetSymbolAddress(&p, sym);
    return (float*)p;
}

extern "C" void kernel_launch(void* const* d_in, const int* in_sizes, int n_in,
                              void* d_out, int out_size) {
    (void)in_sizes; (void)n_in; (void)out_size;
    const float* x      = (const float*)d_in[0];
    const float* pos    = (const float*)d_in[1];
    const float* ln1_g  = (const float*)d_in[2];
    const float* ln1_b  = (const float*)d_in[3];
    const float* qkv_w  = (const float*)d_in[4];
    const float* proj_w = (const float*)d_in[5];
    const float* proj_b = (const float*)d_in[6];
    const float* cp1_dw = (const float*)d_in[7];
    const float* cp1_db = (const float*)d_in[8];
    const float* cp1_cw = (const float*)d_in[9];
    const float* cp1_cb = (const float*)d_in[10];
    const float* cp1_uw = (const float*)d_in[11];
    const float* cp1_ub = (const float*)d_in[12];
    const float* ln2_g  = (const float*)d_in[13];
    const float* ln2_b  = (const float*)d_in[14];
    const float* ff_w1  = (const float*)d_in[15];
    const float* ff_b1  = (const float*)d_in[16];
    const float* ff_w2  = (const float*)d_in[17];
    const float* ff_b2  = (const float*)d_in[18];
    const float* cp2_dw = (const float*)d_in[19];
    const float* cp2_db = (const float*)d_in[20];
    const float* cp2_cw = (const float*)d_in[21];
    const float* cp2_cb = (const float*)d_in[22];
    const float* cp2_uw = (const float*)d_in[23];
    const float* cp2_ub = (const float*)d_in[24];
    float* out = (float*)d_out;

    float* bx    = symaddr(g_x);
    float* bh    = symaddr(g_h);
    float* bqkv  = symaddr(g_qkv);
    float* bao   = symaddr(g_ao);
    float* bp1   = symaddr(g_p1);
    float* bmlp  = symaddr(g_mlp);
    float* bd    = symaddr(g_d);
    float* bc    = symaddr(g_c);
    float* wqkvT = symaddr(g_wqkvT);
    float* wprojT= symaddr(g_wprojT);
    float* wff1T = symaddr(g_wff1T);
    float* wff2T = symaddr(g_wff2T);

    const int GEMM_SMEM = 4 * ABYTES;  // 73728
    cudaFuncSetAttribute(tc_gemm<0>, cudaFuncAttributeMaxDynamicSharedMemorySize, GEMM_SMEM);
    cudaFuncSetAttribute(tc_gemm<1>, cudaFuncAttributeMaxDynamicSharedMemorySize, GEMM_SMEM);
    cudaFuncSetAttribute(tc_gemm<2>, cudaFuncAttributeMaxDynamicSharedMemorySize, GEMM_SMEM);
    cudaFuncSetAttribute(flash_attn, cudaFuncAttributeMaxDynamicSharedMemorySize, FA_SMEM);

    const int n4 = (MROWS * CC) / 4;

    // weight transposes [K,N] -> [N,K] (tf32 rounded)
    transpose_k<<<dim3(1536 / 32, 512 / 32), dim3(32, 8)>>>(qkv_w, wqkvT, 512, 1536);
    transpose_k<<<dim3(512 / 32, 512 / 32), dim3(32, 8)>>>(proj_w, wprojT, 512, 512);
    transpose_k<<<dim3(4096 / 32, 512 / 32), dim3(32, 8)>>>(ff_w1, wff1T, 512, 4096);
    transpose_k<<<dim3(512 / 32, 4096 / 32), dim3(32, 8)>>>(ff_w2, wff2T, 4096, 512);

    // x = x + pos ; h = LN1(x)
    add_kernel<<<(n4 + 255) / 256, 256>>>((const float4*)x, (const float4*)pos, (float4*)bx, n4);
    ln512<<<MROWS, 256>>>(bx, ln1_g, ln1_b, bh);

    // qkv = h @ qkv_w
    tc_gemm<0><<<dim3(12, 128), 256, GEMM_SMEM>>>(bh, wqkvT, nullptr, bqkv, MROWS, 3 * CC, CC);

    // fused attention
    flash_attn<<<dim3(4, BB * HH), 256, FA_SMEM>>>(bqkv, bao);

    // proj
    tc_gemm<1><<<dim3(4, 128), 256, GEMM_SMEM>>>(bao, wprojT, proj_b, bp1, MROWS, CC, CC);

    // convpass 1
    down_kernel<<<MROWS / 8, 256>>>(bh, cp1_dw, cp1_db, bd);
    conv3d_kernel<<<MROWS * ADIM / 256, 256>>>(bd, cp1_cw, cp1_cb, bc);
    up_combine<<<MROWS, 256>>>(bc, cp1_uw, cp1_ub, bx, bp1, bx);

    // h = LN2(x) ; FFN
    ln512<<<MROWS, 256>>>(bx, ln2_g, ln2_b, bh);
    tc_gemm<2><<<dim3(32, 128), 256, GEMM_SMEM>>>(bh, wff1T, ff_b1, bmlp, MROWS, MLPD, CC);
    tc_gemm<1><<<dim3(4, 128), 256, GEMM_SMEM>>>(bmlp, wff2T, ff_b2, bp1, MROWS, CC, MLPD);

    // convpass 2 + final combine
    down_kernel<<<MROWS / 8, 256>>>(bh, cp2_dw, cp2_db, bd);
    conv3d_kernel<<<MROWS * ADIM / 256, 256>>>(bd, cp2_cw, cp2_cb, bc);
    up_combine<<<MROWS, 256>>>(bc, cp2_uw, cp2_ub, bx, bp1, out);
}

// round 5
// speedup vs baseline: 4.4592x; 1.3628x over previous
#include <cuda_runtime.h>
#include <cuda_bf16.h>
#include <cstdint>

// ---------------- problem constants ----------------
#define BB    32
#define NN    512
#define CC    512
#define HH    8
#define DHD   64
#define ADIM  8
#define MLPD  4096
#define MROWS (BB*NN)          // 16384
#define SCALE 0.125f           // 64^-0.5

// ---------------- static device scratch ----------------
__device__ __align__(16) float g_x  [(size_t)MROWS*CC];
__device__ __align__(16) float g_h  [(size_t)MROWS*CC];           // LN1 out (tf32)
__device__ __align__(16) __nv_bfloat16 g_hb[(size_t)MROWS*CC];    // LN2 out (bf16)
__device__ __align__(16) float g_qkv[(size_t)MROWS*3*CC];
__device__ __align__(16) float g_ao [(size_t)MROWS*CC];
__device__ __align__(16) float g_p1 [(size_t)MROWS*CC];
__device__ __align__(16) __nv_bfloat16 g_mlpb[(size_t)MROWS*MLPD]; // ff1 out (bf16)
__device__ __align__(16) float g_d  [(size_t)MROWS*ADIM];
__device__ __align__(16) float g_c  [(size_t)MROWS*ADIM];
// transposed weights [N,K]
__device__ __align__(16) float g_wqkvT[(size_t)3*CC*CC];
__device__ __align__(16) float g_wprojT[(size_t)CC*CC];
__device__ __align__(16) __nv_bfloat16 g_wff1T[(size_t)MLPD*CC];
__device__ __align__(16) __nv_bfloat16 g_wff2T[(size_t)CC*MLPD];

// ---------------- helpers ----------------
__device__ __forceinline__ float qgelu(float v) { return v / (1.0f + __expf(-1.702f * v)); }
__device__ __forceinline__ float gelu_exact(float v) { return 0.5f * v * (1.0f + erff(v * 0.70710678118654752f)); }
__device__ __forceinline__ float to_tf32(float x) {
    float r; asm("cvt.rna.tf32.f32 %0, %1;" : "=f"(r) : "f"(x)); return r;
}
__device__ __forceinline__ uint32_t smem_u32(const void* p) {
    uint32_t a;
    asm("{ .reg .u64 t; cvta.to.shared.u64 t, %1; cvt.u32.u64 %0, t; }" : "=r"(a) : "l"(p));
    return a;
}
__device__ __forceinline__ void cp16(uint32_t saddr, const void* g) {
    asm volatile("cp.async.cg.shared.global [%0], [%1], 16;" :: "r"(saddr), "l"(g));
}
__device__ __forceinline__ void mma_tf32(float d[4], const uint32_t a[4], const uint32_t b[2]) {
    asm volatile("mma.sync.aligned.m16n8k8.row.col.f32.tf32.tf32.f32 "
        "{%0,%1,%2,%3}, {%4,%5,%6,%7}, {%8,%9}, {%0,%1,%2,%3};"
        : "+f"(d[0]), "+f"(d[1]), "+f"(d[2]), "+f"(d[3])
        : "r"(a[0]), "r"(a[1]), "r"(a[2]), "r"(a[3]), "r"(b[0]), "r"(b[1]));
}
__device__ __forceinline__ void mma_bf16(float d[4], const uint32_t a[4], const uint32_t b[2]) {
    asm volatile("mma.sync.aligned.m16n8k16.row.col.f32.bf16.bf16.f32 "
        "{%0,%1,%2,%3}, {%4,%5,%6,%7}, {%8,%9}, {%0,%1,%2,%3};"
        : "+f"(d[0]), "+f"(d[1]), "+f"(d[2]), "+f"(d[3])
        : "r"(a[0]), "r"(a[1]), "r"(a[2]), "r"(a[3]), "r"(b[0]), "r"(b[1]));
}
__device__ __forceinline__ uint32_t pack_bf16(float a, float b) {
    __nv_bfloat162 v = __floats2bfloat162_rn(a, b);
    return *reinterpret_cast<uint32_t*>(&v);
}

__device__ __forceinline__ float blockReduceSum256(float v) {
    __shared__ float sh[8];
    int lane = threadIdx.x & 31, w = threadIdx.x >> 5;
    #pragma unroll
    for (int o = 16; o > 0; o >>= 1) v += __shfl_down_sync(0xffffffffu, v, o);
    if (lane == 0) sh[w] = v;
    __syncthreads();
    if (threadIdx.x < 8) {
        float t = sh[threadIdx.x];
        t += __shfl_down_sync(0xffu, t, 4);
        t += __shfl_down_sync(0xffu, t, 2);
        t += __shfl_down_sync(0xffu, t, 1);
        if (threadIdx.x == 0) sh[0] = t;
    }
    __syncthreads();
    float r = sh[0];
    __syncthreads();
    return r;
}

// ---------------- fused (x+pos) + LN1 ----------------
__global__ __launch_bounds__(256) void add_ln(const float* __restrict__ xin,
                                              const float* __restrict__ pos,
                                              const float* __restrict__ g,
                                              const float* __restrict__ b,
                                              float* __restrict__ xout,
                                              float* __restrict__ hout) {
    size_t row = blockIdx.x;
    int tid = threadIdx.x;
    float v0 = xin[row * CC + tid]       + pos[row * CC + tid];
    float v1 = xin[row * CC + tid + 256] + pos[row * CC + tid + 256];
    xout[row * CC + tid]       = v0;
    xout[row * CC + tid + 256] = v1;
    float mean = blockReduceSum256(v0 + v1) * (1.0f / 512.0f);
    float d0 = v0 - mean, d1 = v1 - mean;
    float var = blockReduceSum256(d0 * d0 + d1 * d1) * (1.0f / 512.0f);
    float inv = rsqrtf(var + 1e-5f);
    hout[row * CC + tid]       = to_tf32(d0 * inv * g[tid]       + b[tid]);
    hout[row * CC + tid + 256] = to_tf32(d1 * inv * g[tid + 256] + b[tid + 256]);
}

// ---------------- transposes ----------------
__global__ void transpose_k(const float* __restrict__ in, float* __restrict__ out,
                            int R, int Cc) {
    __shared__ float t[32][33];
    int bx = blockIdx.x * 32, by = blockIdx.y * 32;
    #pragma unroll
    for (int i = 0; i < 32; i += 8)
        t[threadIdx.y + i][threadIdx.x] = in[(size_t)(by + threadIdx.y + i) * Cc + bx + threadIdx.x];
    __syncthreads();
    #pragma unroll
    for (int i = 0; i < 32; i += 8)
        out[(size_t)(bx + threadIdx.y + i) * R + by + threadIdx.x] =
            to_tf32(t[threadIdx.x][threadIdx.y + i]);
}
__global__ void transpose_k_bf16(const float* __restrict__ in, __nv_bfloat16* __restrict__ out,
                                 int R, int Cc) {
    __shared__ float t[32][33];
    int bx = blockIdx.x * 32, by = blockIdx.y * 32;
    #pragma unroll
    for (int i = 0; i < 32; i += 8)
        t[threadIdx.y + i][threadIdx.x] = in[(size_t)(by + threadIdx.y + i) * Cc + bx + threadIdx.x];
    __syncthreads();
    #pragma unroll
    for (int i = 0; i < 32; i += 8)
        out[(size_t)(bx + threadIdx.y + i) * R + by + threadIdx.x] =
            __float2bfloat16_rn(t[threadIdx.x][threadIdx.y + i]);
}

// ---------------- tf32 mma GEMM (qkv, proj) ----------------
#define SMS 36
#define ABYTES (128*SMS*4)
template<int EPI>   // 0: none, 1: +bias
__global__ __launch_bounds__(256, 2) void tc_gemm(const float* __restrict__ A,
                                                  const float* __restrict__ BT,
                                                  const float* __restrict__ bias,
                                                  float* __restrict__ C,
                                                  int M, int N, int K) {
    extern __shared__ char smem[];
    const uint32_t sb = smem_u32(smem);
    const int tid = threadIdx.x;
    const int lane = tid & 31;
    const int w = tid >> 5;
    const int wm = w & 1, wn = w >> 1;
    const int g = lane >> 2, t = lane & 3;
    const int cRow = blockIdx.y * 128;
    const int cCol = blockIdx.x * 128;
    const int r_st = tid >> 3;
    const int c_st = (tid & 7) << 2;

    float acc[4][4][4] = {};

    auto stage = [&](int kt) {
        const int k0 = kt << 5;
        const uint32_t ab = sb + (kt & 1) * ABYTES;
        const uint32_t bb = sb + 2 * ABYTES + (kt & 1) * ABYTES;
        #pragma unroll
        for (int i = 0; i < 4; ++i) {
            int r = r_st + i * 32;
            cp16(ab + (uint32_t)(r * SMS + c_st) * 4, A + (size_t)(cRow + r) * K + k0 + c_st);
            cp16(bb + (uint32_t)(r * SMS + c_st) * 4, BT + (size_t)(cCol + r) * K + k0 + c_st);
        }
        asm volatile("cp.async.commit_group;" ::: "memory");
    };

    const int NC = K >> 5;
    stage(0);
    for (int c = 0; c < NC; ++c) {
        if (c + 1 < NC) { stage(c + 1); asm volatile("cp.async.wait_group 1;" ::: "memory"); }
        else            { asm volatile("cp.async.wait_group 0;" ::: "memory"); }
        __syncthreads();
        const float* As = (const float*)(smem + (c & 1) * ABYTES);
        const float* Bs = (const float*)(smem + 2 * ABYTES + (c & 1) * ABYTES);
        #pragma unroll
        for (int ks = 0; ks < 4; ++ks) {
            const int kk = ks * 8 + t;
            uint32_t af[4][4], bf[4][2];
            #pragma unroll
            for (int mf = 0; mf < 4; ++mf) {
                const float* ap = As + (wm * 64 + mf * 16 + g) * SMS + kk;
                af[mf][0] = __float_as_uint(ap[0]);
                af[mf][1] = __float_as_uint(ap[8 * SMS]);
                af[mf][2] = __float_as_uint(ap[4]);
                af[mf][3] = __float_as_uint(ap[8 * SMS + 4]);
            }
            #pragma unroll
            for (int nf = 0; nf < 4; ++nf) {
                const float* bp = Bs + (wn * 32 + nf * 8 + g) * SMS + kk;
                bf[nf][0] = __float_as_uint(bp[0]);
                bf[nf][1] = __float_as_uint(bp[4]);
            }
            #pragma unroll
            for (int mf = 0; mf < 4; ++mf)
                #pragma unroll
                for (int nf = 0; nf < 4; ++nf)
                    mma_tf32(acc[mf][nf], af[mf], bf[nf]);
        }
        __syncthreads();
    }

    #pragma unroll
    for (int mf = 0; mf < 4; ++mf) {
        size_t row0 = (size_t)(cRow + wm * 64 + mf * 16 + g);
        size_t row1 = row0 + 8;
        #pragma unroll
        for (int nf = 0; nf < 4; ++nf) {
            int col = cCol + wn * 32 + nf * 8 + 2 * t;
            float v0 = acc[mf][nf][0], v1 = acc[mf][nf][1];
            float v2 = acc[mf][nf][2], v3 = acc[mf][nf][3];
            if (EPI >= 1) {
                float b0 = bias[col], b1 = bias[col + 1];
                v0 += b0; v1 += b1; v2 += b0; v3 += b1;
            }
            *reinterpret_cast<float2*>(&C[row0 * N + col]) = make_float2(v0, v1);
            *reinterpret_cast<float2*>(&C[row1 * N + col]) = make_float2(v2, v3);
        }
    }
}

// ---------------- bf16 mma GEMM (ff1, ff2) ----------------
// BK=64 bf16, smem row stride 72 elems (=36 words). EPI: 1 = +bias->fp32, 2 = +bias+gelu->bf16
#define BSMS_E 72
#define BBYTES (128*BSMS_E*2)   // 18432, same as ABYTES
template<int EPI>
__global__ __launch_bounds__(256, 2) void tc_gemm_bf16(const __nv_bfloat16* __restrict__ A,
                                                       const __nv_bfloat16* __restrict__ BT,
                                                       const float* __restrict__ bias,
                                                       void* __restrict__ Cv,
                                                       int M, int N, int K) {
    extern __shared__ char smem[];
    const uint32_t sb = smem_u32(smem);
    const int tid = threadIdx.x;
    const int lane = tid & 31;
    const int w = tid >> 5;
    const int wm = w & 1, wn = w >> 1;
    const int g = lane >> 2, t = lane & 3;
    const int cRow = blockIdx.y * 128;
    const int cCol = blockIdx.x * 128;
    const int r_st = tid >> 3;
    const int c_st = (tid & 7) << 3;        // element col, 8 bf16 per cp16

    float acc[4][4][4] = {};

    auto stage = [&](int kt) {
        const int k0 = kt << 6;
        const uint32_t ab = sb + (kt & 1) * BBYTES;
        const uint32_t bb = sb + 2 * BBYTES + (kt & 1) * BBYTES;
        #pragma unroll
        for (int i = 0; i < 4; ++i) {
            int r = r_st + i * 32;
            cp16(ab + (uint32_t)(r * BSMS_E + c_st) * 2, A + (size_t)(cRow + r) * K + k0 + c_st);
            cp16(bb + (uint32_t)(r * BSMS_E + c_st) * 2, BT + (size_t)(cCol + r) * K + k0 + c_st);
        }
        asm volatile("cp.async.commit_group;" ::: "memory");
    };

    const int NC = K >> 6;
    stage(0);
    for (int c = 0; c < NC; ++c) {
        if (c + 1 < NC) { stage(c + 1); asm volatile("cp.async.wait_group 1;" ::: "memory"); }
        else            { asm volatile("cp.async.wait_group 0;" ::: "memory"); }
        __syncthreads();
        const uint32_t* As = (const uint32_t*)(smem + (c & 1) * BBYTES);
        const uint32_t* Bs = (const uint32_t*)(smem + 2 * BBYTES + (c & 1) * BBYTES);
        #pragma unroll
        for (int ks = 0; ks < 4; ++ks) {        // 4 x k16 steps
            const int kw = ks * 8 + t;          // word offset in row
            uint32_t af[4][4], bf[4][2];
            #pragma unroll
            for (int mf = 0; mf < 4; ++mf) {
                const uint32_t* ap = As + (wm * 64 + mf * 16 + g) * 36 + kw;
                af[mf][0] = ap[0];
                af[mf][1] = ap[8 * 36];
                af[mf][2] = ap[4];
                af[mf][3] = ap[8 * 36 + 4];
            }
            #pragma unroll
            for (int nf = 0; nf < 4; ++nf) {
                const uint32_t* bp = Bs + (wn * 32 + nf * 8 + g) * 36 + kw;
                bf[nf][0] = bp[0];
                bf[nf][1] = bp[4];
            }
            #pragma unroll
            for (int mf = 0; mf < 4; ++mf)
                #pragma unroll
                for (int nf = 0; nf < 4; ++nf)
                    mma_bf16(acc[mf][nf], af[mf], bf[nf]);
        }
        __syncthreads();
    }

    #pragma unroll
    for (int mf = 0; mf < 4; ++mf) {
        size_t row0 = (size_t)(cRow + wm * 64 + mf * 16 + g);
        size_t row1 = row0 + 8;
        #pragma unroll
        for (int nf = 0; nf < 4; ++nf) {
            int col = cCol + wn * 32 + nf * 8 + 2 * t;
            float b0 = bias[col], b1 = bias[col + 1];
            float v0 = acc[mf][nf][0] + b0, v1 = acc[mf][nf][1] + b1;
            float v2 = acc[mf][nf][2] + b0, v3 = acc[mf][nf][3] + b1;
            if (EPI == 2) {
                uint32_t* C = (uint32_t*)Cv;
                *(C + (row0 * N + col) / 2) = pack_bf16(gelu_exact(v0), gelu_exact(v1));
                *(C + (row1 * N + col) / 2) = pack_bf16(gelu_exact(v2), gelu_exact(v3));
            } else {
                float* C = (float*)Cv;
                *reinterpret_cast<float2*>(&C[row0 * N + col]) = make_float2(v0, v1);
                *reinterpret_cast<float2*>(&C[row1 * N + col]) = make_float2(v2, v3);
            }
        }
    }
}

// ---------------- fused flash attention (tf32 mma) ----------------
#define FA_SMEM ((128*68 + 64*68 + 64*68) * 4)
__global__ __launch_bounds__(256) void flash_attn(const float* __restrict__ qkv,
                                                  float* __restrict__ O) {
    extern __shared__ float fs[];
    float* Ps = fs;
    float* Ks = fs + 128 * 68;
    float* Vt = Ks + 64 * 68;
    const int tid = threadIdx.x;
    const int lane = tid & 31;
    const int w = tid >> 5;
    const int g = lane >> 2, t = lane & 3;
    const int qt = blockIdx.x;
    const int bh = blockIdx.y;
    const int b = bh >> 3, h = bh & 7;
    const int r0 = w * 16 + g;

    const size_t qbase = ((size_t)b * NN + qt * 128) * 1536 + h * 64;
    #pragma unroll
    for (int i = 0; i < 8; ++i) {
        int lin = tid + 256 * i;
        int r = lin >> 4, c4 = (lin & 15) << 2;
        float4 q = *reinterpret_cast<const float4*>(qkv + qbase + (size_t)r * 1536 + c4);
        float* d = Ps + r * 68 + c4;
        d[0] = to_tf32(q.x * SCALE); d[1] = to_tf32(q.y * SCALE);
        d[2] = to_tf32(q.z * SCALE); d[3] = to_tf32(q.w * SCALE);
    }
    __syncthreads();
    uint32_t qf[8][4];
    #pragma unroll
    for (int ks = 0; ks < 8; ++ks) {
        const float* p = Ps + r0 * 68 + ks * 8 + t;
        qf[ks][0] = __float_as_uint(p[0]);
        qf[ks][1] = __float_as_uint(p[8 * 68]);
        qf[ks][2] = __float_as_uint(p[4]);
        qf[ks][3] = __float_as_uint(p[8 * 68 + 4]);
    }
    __syncthreads();

    float oacc[8][4] = {};
    float m0 = -1e30f, m1 = -1e30f, l0 = 0.f, l1 = 0.f;
    const size_t kbase = (size_t)b * NN * 1536 + 512 + h * 64;
    const size_t vbase = kbase + 512;

    for (int kt = 0; kt < 8; ++kt) {
        #pragma unroll
        for (int i = 0; i < 4; ++i) {
            int lin = tid + 256 * i;
            int r = lin >> 4, c4 = (lin & 15) << 2;
            size_t off = (size_t)(kt * 64 + r) * 1536 + c4;
            float4 kv = *reinterpret_cast<const float4*>(qkv + kbase + off);
            float* d = Ks + r * 68 + c4;
            d[0] = to_tf32(kv.x); d[1] = to_tf32(kv.y);
            d[2] = to_tf32(kv.z); d[3] = to_tf32(kv.w);
            float4 vv = *reinterpret_cast<const float4*>(qkv + vbase + off);
            Vt[(c4 + 0) * 68 + r] = to_tf32(vv.x);
            Vt[(c4 + 1) * 68 + r] = to_tf32(vv.y);
            Vt[(c4 + 2) * 68 + r] = to_tf32(vv.z);
            Vt[(c4 + 3) * 68 + r] = to_tf32(vv.w);
        }
        __syncthreads();

        float sacc[8][4] = {};
        #pragma unroll
        for (int ks = 0; ks < 8; ++ks) {
            #pragma unroll
            for (int nf = 0; nf < 8; ++nf) {
                const float* bp = Ks + (nf * 8 + g) * 68 + ks * 8 + t;
                uint32_t bf[2] = {__float_as_uint(bp[0]), __float_as_uint(bp[4])};
                mma_tf32(sacc[nf], qf[ks], bf);
            }
        }
        float mx0 = -1e30f, mx1 = -1e30f;
        #pragma unroll
        for (int nf = 0; nf < 8; ++nf) {
            mx0 = fmaxf(mx0, fmaxf(sacc[nf][0], sacc[nf][1]));
            mx1 = fmaxf(mx1, fmaxf(sacc[nf][2], sacc[nf][3]));
        }
        mx0 = fmaxf(mx0, __shfl_xor_sync(0xffffffffu, mx0, 1));
        mx0 = fmaxf(mx0, __shfl_xor_sync(0xffffffffu, mx0, 2));
        mx1 = fmaxf(mx1, __shfl_xor_sync(0xffffffffu, mx1, 1));
        mx1 = fmaxf(mx1, __shfl_xor_sync(0xffffffffu, mx1, 2));
        float mn0 = fmaxf(m0, mx0), mn1 = fmaxf(m1, mx1);
        float f0 = __expf(m0 - mn0), f1 = __expf(m1 - mn1);
        m0 = mn0; m1 = mn1;
        float rs0 = 0.f, rs1 = 0.f;
        #pragma unroll
        for (int nf = 0; nf < 8; ++nf) {
            sacc[nf][0] = __expf(sacc[nf][0] - mn0);
            sacc[nf][1] = __expf(sacc[nf][1] - mn0);
            sacc[nf][2] = __expf(sacc[nf][2] - mn1);
            sacc[nf][3] = __expf(sacc[nf][3] - mn1);
            rs0 += sacc[nf][0] + sacc[nf][1];
            rs1 += sacc[nf][2] + sacc[nf][3];
        }
        rs0 += __shfl_xor_sync(0xffffffffu, rs0, 1);
        rs0 += __shfl_xor_sync(0xffffffffu, rs0, 2);
        rs1 += __shfl_xor_sync(0xffffffffu, rs1, 1);
        rs1 += __shfl_xor_sync(0xffffffffu, rs1, 2);
        l0 = l0 * f0 + rs0; l1 = l1 * f1 + rs1;
        #pragma unroll
        for (int nf = 0; nf < 8; ++nf) {
            oacc[nf][0] *= f0; oacc[nf][1] *= f0;
            oacc[nf][2] *= f1; oacc[nf][3] *= f1;
        }
        #pragma unroll
        for (int nf = 0; nf < 8; ++nf) {
            float* pr = Ps + r0 * 68 + nf * 8 + 2 * t;
            *reinterpret_cast<float2*>(pr) =
                make_float2(to_tf32(sacc[nf][0]), to_tf32(sacc[nf][1]));
            *reinterpret_cast<float2*>(pr + 8 * 68) =
                make_float2(to_tf32(sacc[nf][2]), to_tf32(sacc[nf][3]));
        }
        __syncwarp();
        #pragma unroll
        for (int ks = 0; ks < 8; ++ks) {
            const float* ap = Ps + r0 * 68 + ks * 8 + t;
            uint32_t af[4] = {__float_as_uint(ap[0]), __float_as_uint(ap[8 * 68]),
                              __float_as_uint(ap[4]), __float_as_uint(ap[8 * 68 + 4])};
            #pragma unroll
            for (int nf = 0; nf < 8; ++nf) {
                const float* bp = Vt + (nf * 8 + g) * 68 + ks * 8 + t;
                uint32_t bf[2] = {__float_as_uint(bp[0]), __float_as_uint(bp[4])};
                mma_tf32(oacc[nf], af, bf);
            }
        }
        __syncthreads();
    }

    float i0 = 1.0f / l0, i1 = 1.0f / l1;
    size_t orow = (size_t)(b * NN + qt * 128 + r0);
    #pragma unroll
    for (int nf = 0; nf < 8; ++nf) {
        int col = h * 64 + nf * 8 + 2 * t;
        *reinterpret_cast<float2*>(&O[orow * CC + col]) =
            make_float2(to_tf32(oacc[nf][0] * i0), to_tf32(oacc[nf][1] * i0));
        *reinterpret_cast<float2*>(&O[(orow + 8) * CC + col]) =
            make_float2(to_tf32(oacc[nf][2] * i1), to_tf32(oacc[nf][3] * i1));
    }
}

// ---------------- adapter down (templated input type) ----------------
template<typename T>
__global__ __launch_bounds__(256) void down_kernel(const T* __restrict__ h,
                                                   const float* __restrict__ dw,
                                                   const float* __restrict__ db,
                                                   float* __restrict__ out) {
    __shared__ float wsh[512 * 8];
    for (int i = threadIdx.x; i < 4096; i += 256) wsh[i] = dw[i];
    __syncthreads();
    int warp = threadIdx.x >> 5, lane = threadIdx.x & 31;
    int row = blockIdx.x * 8 + warp;
    const T* hp = h + (size_t)row * CC;
    float acc[8] = {};
    for (int k = lane; k < 512; k += 32) {
        float xv = (float)hp[k];
        #pragma unroll
        for (int a = 0; a < 8; ++a) acc[a] += xv * wsh[k * 8 + a];
    }
    #pragma unroll
    for (int a = 0; a < 8; ++a) {
        #pragma unroll
        for (int o = 16; o > 0; o >>= 1)
            acc[a] += __shfl_down_sync(0xffffffffu, acc[a], o);
    }
    if (lane == 0) {
        #pragma unroll
        for (int a = 0; a < 8; ++a)
            out[(size_t)row * 8 + a] = qgelu(acc[a] + db[a]);
    }
}

// ---------------- tiny 3D conv ----------------
__global__ __launch_bounds__(256) void conv3d_kernel(const float* __restrict__ din,
                                                     const float* __restrict__ cw,
                                                     const float* __restrict__ cb,
                                                     float* __restrict__ out) {
    __shared__ float w[1728];
    __shared__ float bsh[8];
    for (int i = threadIdx.x; i < 1728; i += 256) w[i] = cw[i];
    if (threadIdx.x < 8) bsh[threadIdx.x] = cb[threadIdx.x];
    __syncthreads();
    int gid = blockIdx.x * 256 + threadIdx.x;
    int o  = gid & 7;
    int sp = (gid >> 3) & 511;
    int b  = gid >> 12;
    int xx = sp & 7, yy = (sp >> 3) & 7, zz = sp >> 6;
    float acc = bsh[o];
    for (int dz = -1; dz <= 1; ++dz) {
        int z = zz + dz; if ((unsigned)z > 7u) continue;
        for (int dy = -1; dy <= 1; ++dy) {
            int y = yy + dy; if ((unsigned)y > 7u) continue;
            for (int dx = -1; dx <= 1; ++dx) {
                int xc = xx + dx; if ((unsigned)xc > 7u) continue;
                const float* ip = din + ((size_t)b * 512 + z * 64 + y * 8 + xc) * 8;
                const float* wp = w + o * 216 + ((dz + 1) * 3 + (dy + 1)) * 3 + (dx + 1);
                #pragma unroll
                for (int i = 0; i < 8; ++i) acc += ip[i] * wp[i * 27];
            }
        }
    }
    out[gid] = acc;
}

// ---------------- up + combine (+ optional fused LN2 -> bf16) ----------------
__global__ __launch_bounds__(256) void up_combine_ln(const float* __restrict__ cpre,
                                                     const float* __restrict__ uw,
                                                     const float* __restrict__ ub,
                                                     const float* __restrict__ res,
                                                     const float* __restrict__ add1,
                                                     float* __restrict__ out,
                                                     const float* __restrict__ lng,
                                                     const float* __restrict__ lnb,
                                                     __nv_bfloat16* __restrict__ hout) {
    size_t n = blockIdx.x;
    __shared__ float p[8];
    int tid = threadIdx.x;
    if (tid < 8) p[tid] = qgelu(cpre[n * 8 + tid]);
    __syncthreads();
    float vv[2];
    #pragma unroll
    for (int it = 0; it < 2; ++it) {
        int c = tid + it * 256;
        float acc = ub[c];
        #pragma unroll
        for (int a = 0; a < 8; ++a) acc += p[a] * uw[a * 512 + c];
        vv[it] = res[n * CC + c] + add1[n * CC + c] + acc;
        out[n * CC + c] = vv[it];
    }
    float mean = blockReduceSum256(vv[0] + vv[1]) * (1.0f / 512.0f);
    float d0 = vv[0] - mean, d1 = vv[1] - mean;
    float var = blockReduceSum256(d0 * d0 + d1 * d1) * (1.0f / 512.0f);
    float inv = rsqrtf(var + 1e-5f);
    hout[n * CC + tid]       = __float2bfloat16_rn(d0 * inv * lng[tid]       + lnb[tid]);
    hout[n * CC + tid + 256] = __float2bfloat16_rn(d1 * inv * lng[tid + 256] + lnb[tid + 256]);
}

__global__ __launch_bounds__(256) void up_combine(const float* __restrict__ cpre,
                                                  const float* __restrict__ uw,
                                                  const float* __restrict__ ub,
                                                  const float* __restrict__ res,
                                                  const float* __restrict__ add1,
                                                  float* __restrict__ out) {
    size_t n = blockIdx.x;
    __shared__ float p[8];
    int tid = threadIdx.x;
    if (tid < 8) p[tid] = qgelu(cpre[n * 8 + tid]);
    __syncthreads();
    #pragma unroll
    for (int it = 0; it < 2; ++it) {
        int c = tid + it * 256;
        float acc = ub[c];
        #pragma unroll
        for (int a = 0; a < 8; ++a) acc += p[a] * uw[a * 512 + c];
        out[n * CC + c] = res[n * CC + c] + add1[n * CC + c] + acc;
    }
}

// ---------------- launcher ----------------
static float* symaddr(const void* sym) {
    void* p = nullptr;
    cudaGetSymbolAddress(&p, sym);
    return (float*)p;
}

extern "C" void kernel_launch(void* const* d_in, const int* in_sizes, int n_in,
                              void* d_out, int out_size) {
    (void)in_sizes; (void)n_in; (void)out_size;
    const float* x      = (const float*)d_in[0];
    const float* pos    = (const float*)d_in[1];
    const float* ln1_g  = (const float*)d_in[2];
    const float* ln1_b  = (const float*)d_in[3];
    const float* qkv_w  = (const float*)d_in[4];
    const float* proj_w = (const float*)d_in[5];
    const float* proj_b = (const float*)d_in[6];
    const float* cp1_dw = (const float*)d_in[7];
    const float* cp1_db = (const float*)d_in[8];
    const float* cp1_cw = (const float*)d_in[9];
    const float* cp1_cb = (const float*)d_in[10];
    const float* cp1_uw = (const float*)d_in[11];
    const float* cp1_ub = (const float*)d_in[12];
    const float* ln2_g  = (const float*)d_in[13];
    const float* ln2_b  = (const float*)d_in[14];
    const float* ff_w1  = (const float*)d_in[15];
    const float* ff_b1  = (const float*)d_in[16];
    const float* ff_w2  = (const float*)d_in[17];
    const float* ff_b2  = (const float*)d_in[18];
    const float* cp2_dw = (const float*)d_in[19];
    const float* cp2_db = (const float*)d_in[20];
    const float* cp2_cw = (const float*)d_in[21];
    const float* cp2_cb = (const float*)d_in[22];
    const float* cp2_uw = (const float*)d_in[23];
    const float* cp2_ub = (const float*)d_in[24];
    float* out = (float*)d_out;

    float* bx    = symaddr(g_x);
    float* bh    = symaddr(g_h);
    __nv_bfloat16* bhb = (__nv_bfloat16*)symaddr(g_hb);
    float* bqkv  = symaddr(g_qkv);
    float* bao   = symaddr(g_ao);
    float* bp1   = symaddr(g_p1);
    __nv_bfloat16* bmlpb = (__nv_bfloat16*)symaddr(g_mlpb);
    float* bd    = symaddr(g_d);
    float* bc    = symaddr(g_c);
    float* wqkvT = symaddr(g_wqkvT);
    float* wprojT= symaddr(g_wprojT);
    __nv_bfloat16* wff1T = (__nv_bfloat16*)symaddr(g_wff1T);
    __nv_bfloat16* wff2T = (__nv_bfloat16*)symaddr(g_wff2T);

    const int GEMM_SMEM = 4 * ABYTES;  // 73728
    cudaFuncSetAttribute(tc_gemm<0>, cudaFuncAttributeMaxDynamicSharedMemorySize, GEMM_SMEM);
    cudaFuncSetAttribute(tc_gemm<1>, cudaFuncAttributeMaxDynamicSharedMemorySize, GEMM_SMEM);
    cudaFuncSetAttribute(tc_gemm_bf16<1>, cudaFuncAttributeMaxDynamicSharedMemorySize, GEMM_SMEM);
    cudaFuncSetAttribute(tc_gemm_bf16<2>, cudaFuncAttributeMaxDynamicSharedMemorySize, GEMM_SMEM);
    cudaFuncSetAttribute(flash_attn, cudaFuncAttributeMaxDynamicSharedMemorySize, FA_SMEM);

    // weight transposes [K,N] -> [N,K]
    transpose_k<<<dim3(1536 / 32, 512 / 32), dim3(32, 8)>>>(qkv_w, wqkvT, 512, 1536);
    transpose_k<<<dim3(512 / 32, 512 / 32), dim3(32, 8)>>>(proj_w, wprojT, 512, 512);
    transpose_k_bf16<<<dim3(4096 / 32, 512 / 32), dim3(32, 8)>>>(ff_w1, wff1T, 512, 4096);
    transpose_k_bf16<<<dim3(512 / 32, 4096 / 32), dim3(32, 8)>>>(ff_w2, wff2T, 4096, 512);

    // x = x + pos ; h = LN1(x)   (fused)
    add_ln<<<MROWS, 256>>>(x, pos, ln1_g, ln1_b, bx, bh);

    // qkv = h @ qkv_w (tf32)
    tc_gemm<0><<<dim3(12, 128), 256, GEMM_SMEM>>>(bh, wqkvT, nullptr, bqkv, MROWS, 3 * CC, CC);

    // fused attention
    flash_attn<<<dim3(4, BB * HH), 256, FA_SMEM>>>(bqkv, bao);

    // proj (tf32)
    tc_gemm<1><<<dim3(4, 128), 256, GEMM_SMEM>>>(bao, wprojT, proj_b, bp1, MROWS, CC, CC);

    // convpass 1
    down_kernel<float><<<MROWS / 8, 256>>>(bh, cp1_dw, cp1_db, bd);
    conv3d_kernel<<<MROWS * ADIM / 256, 256>>>(bd, cp1_cw, cp1_cb, bc);
    // x = x + proj + up ; h2 = LN2(x) -> bf16  (fused)
    up_combine_ln<<<MROWS, 256>>>(bc, cp1_uw, cp1_ub, bx, bp1, bx, ln2_g, ln2_b, bhb);

    // FFN (bf16 mma)
    tc_gemm_bf16<2><<<dim3(32, 128), 256, GEMM_SMEM>>>(bhb, wff1T, ff_b1, bmlpb, MROWS, MLPD, CC);
    tc_gemm_bf16<1><<<dim3(4, 128), 256, GEMM_SMEM>>>(bmlpb, wff2T, ff_b2, bp1, MROWS, CC, MLPD);

    // convpass 2 + final combine
    down_kernel<__nv_bfloat16><<<MROWS / 8, 256>>>(bhb, cp2_dw, cp2_db, bd);
    conv3d_kernel<<<MROWS * ADIM / 256, 256>>>(bd, cp2_cw, cp2_cb, bc);
    up_combine<<<MROWS, 256>>>(bc, cp2_uw, cp2_ub, bx, bp1, out);
}

// round 6
// speedup vs baseline: 4.4655x; 1.0014x over previous
#include <cuda_runtime.h>
#include <cuda_bf16.h>
#include <cstdint>

// ---------------- problem constants ----------------
#define BB    32
#define NN    512
#define CC    512
#define HH    8
#define DHD   64
#define ADIM  8
#define MLPD  4096
#define MROWS (BB*NN)          // 16384
#define SCALE 0.125f           // 64^-0.5

// ---------------- static device scratch ----------------
__device__ __align__(16) float g_x  [(size_t)MROWS*CC];
__device__ __align__(16) float g_h  [(size_t)MROWS*CC];           // LN1 out (tf32)
__device__ __align__(16) __nv_bfloat16 g_hb[(size_t)MROWS*CC];    // LN2 out (bf16)
__device__ __align__(16) float g_qkv[(size_t)MROWS*3*CC];
__device__ __align__(16) float g_ao [(size_t)MROWS*CC];
__device__ __align__(16) __nv_bfloat16 g_mlpb[(size_t)MROWS*MLPD]; // ff1 out (bf16)
__device__ __align__(16) float g_d  [(size_t)MROWS*ADIM];
__device__ __align__(16) float g_c  [(size_t)MROWS*ADIM];
// transposed weights [N,K]
__device__ __align__(16) float g_wqkvT[(size_t)3*CC*CC];
__device__ __align__(16) float g_wprojT[(size_t)CC*CC];
__device__ __align__(16) __nv_bfloat16 g_wff1T[(size_t)MLPD*CC];
__device__ __align__(16) __nv_bfloat16 g_wff2T[(size_t)CC*MLPD];

// ---------------- helpers ----------------
__device__ __forceinline__ float qgelu(float v) { return v / (1.0f + __expf(-1.702f * v)); }
__device__ __forceinline__ float gelu_exact(float v) { return 0.5f * v * (1.0f + erff(v * 0.70710678118654752f)); }
__device__ __forceinline__ float to_tf32(float x) {
    float r; asm("cvt.rna.tf32.f32 %0, %1;" : "=f"(r) : "f"(x)); return r;
}
__device__ __forceinline__ uint32_t smem_u32(const void* p) {
    uint32_t a;
    asm("{ .reg .u64 t; cvta.to.shared.u64 t, %1; cvt.u32.u64 %0, t; }" : "=r"(a) : "l"(p));
    return a;
}
__device__ __forceinline__ void cp16(uint32_t saddr, const void* g) {
    asm volatile("cp.async.cg.shared.global [%0], [%1], 16;" :: "r"(saddr), "l"(g));
}
__device__ __forceinline__ void mma_tf32(float d[4], const uint32_t a[4], const uint32_t b[2]) {
    asm volatile("mma.sync.aligned.m16n8k8.row.col.f32.tf32.tf32.f32 "
        "{%0,%1,%2,%3}, {%4,%5,%6,%7}, {%8,%9}, {%0,%1,%2,%3};"
        : "+f"(d[0]), "+f"(d[1]), "+f"(d[2]), "+f"(d[3])
        : "r"(a[0]), "r"(a[1]), "r"(a[2]), "r"(a[3]), "r"(b[0]), "r"(b[1]));
}
__device__ __forceinline__ void mma_bf16(float d[4], const uint32_t a[4], const uint32_t b[2]) {
    asm volatile("mma.sync.aligned.m16n8k16.row.col.f32.bf16.bf16.f32 "
        "{%0,%1,%2,%3}, {%4,%5,%6,%7}, {%8,%9}, {%0,%1,%2,%3};"
        : "+f"(d[0]), "+f"(d[1]), "+f"(d[2]), "+f"(d[3])
        : "r"(a[0]), "r"(a[1]), "r"(a[2]), "r"(a[3]), "r"(b[0]), "r"(b[1]));
}
#define LDSM_X4(r0, r1, r2, r3, addr) \
    asm volatile("ldmatrix.sync.aligned.m8n8.x4.shared.b16 {%0,%1,%2,%3}, [%4];" \
        : "=r"(r0), "=r"(r1), "=r"(r2), "=r"(r3) : "r"(addr))
__device__ __forceinline__ uint32_t pack_bf16(float a, float b) {
    __nv_bfloat162 v = __floats2bfloat162_rn(a, b);
    return *reinterpret_cast<uint32_t*>(&v);
}

__device__ __forceinline__ float blockReduceSum256(float v) {
    __shared__ float sh[8];
    int lane = threadIdx.x & 31, w = threadIdx.x >> 5;
    #pragma unroll
    for (int o = 16; o > 0; o >>= 1) v += __shfl_down_sync(0xffffffffu, v, o);
    if (lane == 0) sh[w] = v;
    __syncthreads();
    if (threadIdx.x < 8) {
        float t = sh[threadIdx.x];
        t += __shfl_down_sync(0xffu, t, 4);
        t += __shfl_down_sync(0xffu, t, 2);
        t += __shfl_down_sync(0xffu, t, 1);
        if (threadIdx.x == 0) sh[0] = t;
    }
    __syncthreads();
    float r = sh[0];
    __syncthreads();
    return r;
}

// ---------------- fused (x+pos) + LN1 ----------------
__global__ __launch_bounds__(256) void add_ln(const float* __restrict__ xin,
                                              const float* __restrict__ pos,
                                              const float* __restrict__ g,
                                              const float* __restrict__ b,
                                              float* __restrict__ xout,
                                              float* __restrict__ hout) {
    size_t row = blockIdx.x;
    int tid = threadIdx.x;
    float v0 = xin[row * CC + tid]       + pos[row * CC + tid];
    float v1 = xin[row * CC + tid + 256] + pos[row * CC + tid + 256];
    xout[row * CC + tid]       = v0;
    xout[row * CC + tid + 256] = v1;
    float mean = blockReduceSum256(v0 + v1) * (1.0f / 512.0f);
    float d0 = v0 - mean, d1 = v1 - mean;
    float var = blockReduceSum256(d0 * d0 + d1 * d1) * (1.0f / 512.0f);
    float inv = rsqrtf(var + 1e-5f);
    hout[row * CC + tid]       = to_tf32(d0 * inv * g[tid]       + b[tid]);
    hout[row * CC + tid + 256] = to_tf32(d1 * inv * g[tid + 256] + b[tid + 256]);
}

// ---------------- LN2 (f32 in -> bf16 out) ----------------
__global__ __launch_bounds__(256) void ln_bf16(const float* __restrict__ in,
                                               const float* __restrict__ g,
                                               const float* __restrict__ b,
                                               __nv_bfloat16* __restrict__ out) {
    size_t row = blockIdx.x;
    int tid = threadIdx.x;
    float v0 = in[row * CC + tid], v1 = in[row * CC + tid + 256];
    float mean = blockReduceSum256(v0 + v1) * (1.0f / 512.0f);
    float d0 = v0 - mean, d1 = v1 - mean;
    float var = blockReduceSum256(d0 * d0 + d1 * d1) * (1.0f / 512.0f);
    float inv = rsqrtf(var + 1e-5f);
    out[row * CC + tid]       = __float2bfloat16_rn(d0 * inv * g[tid]       + b[tid]);
    out[row * CC + tid + 256] = __float2bfloat16_rn(d1 * inv * g[tid + 256] + b[tid + 256]);
}

// ---------------- transposes ----------------
__global__ void transpose_k(const float* __restrict__ in, float* __restrict__ out,
                            int R, int Cc) {
    __shared__ float t[32][33];
    int bx = blockIdx.x * 32, by = blockIdx.y * 32;
    #pragma unroll
    for (int i = 0; i < 32; i += 8)
        t[threadIdx.y + i][threadIdx.x] = in[(size_t)(by + threadIdx.y + i) * Cc + bx + threadIdx.x];
    __syncthreads();
    #pragma unroll
    for (int i = 0; i < 32; i += 8)
        out[(size_t)(bx + threadIdx.y + i) * R + by + threadIdx.x] =
            to_tf32(t[threadIdx.x][threadIdx.y + i]);
}
__global__ void transpose_k_bf16(const float* __restrict__ in, __nv_bfloat16* __restrict__ out,
                                 int R, int Cc) {
    __shared__ float t[32][33];
    int bx = blockIdx.x * 32, by = blockIdx.y * 32;
    #pragma unroll
    for (int i = 0; i < 32; i += 8)
        t[threadIdx.y + i][threadIdx.x] = in[(size_t)(by + threadIdx.y + i) * Cc + bx + threadIdx.x];
    __syncthreads();
    #pragma unroll
    for (int i = 0; i < 32; i += 8)
        out[(size_t)(bx + threadIdx.y + i) * R + by + threadIdx.x] =
            __float2bfloat16_rn(t[threadIdx.x][threadIdx.y + i]);
}

// ---------------- tf32 mma GEMM ----------------
// EPI 0: plain store. EPI 2: +(bias+ub) +res +adapter_up, in-place combine (proj).
#define SMS 36
#define ABYTES (128*SMS*4)
template<int EPI>
__global__ __launch_bounds__(256, 2) void tc_gemm(const float* __restrict__ A,
                                                  const float* __restrict__ BT,
                                                  const float* __restrict__ bias,
                                                  float* __restrict__ C,
                                                  int M, int N, int K,
                                                  const float* __restrict__ res,
                                                  const float* __restrict__ cpre,
                                                  const float* __restrict__ uw,
                                                  const float* __restrict__ ub) {
    extern __shared__ char smem[];
    const uint32_t sb = smem_u32(smem);
    const int tid = threadIdx.x;
    const int lane = tid & 31;
    const int w = tid >> 5;
    const int wm = w & 1, wn = w >> 1;
    const int g = lane >> 2, t = lane & 3;
    const int cRow = blockIdx.y * 128;
    const int cCol = blockIdx.x * 128;
    const int r_st = tid >> 3;
    const int c_st = (tid & 7) << 2;

    float acc[4][4][4] = {};

    auto stage = [&](int kt) {
        const int k0 = kt << 5;
        const uint32_t ab = sb + (kt & 1) * ABYTES;
        const uint32_t bb = sb + 2 * ABYTES + (kt & 1) * ABYTES;
        #pragma unroll
        for (int i = 0; i < 4; ++i) {
            int r = r_st + i * 32;
            cp16(ab + (uint32_t)(r * SMS + c_st) * 4, A + (size_t)(cRow + r) * K + k0 + c_st);
            cp16(bb + (uint32_t)(r * SMS + c_st) * 4, BT + (size_t)(cCol + r) * K + k0 + c_st);
        }
        asm volatile("cp.async.commit_group;" ::: "memory");
    };

    const int NC = K >> 5;
    stage(0);
    for (int c = 0; c < NC; ++c) {
        if (c + 1 < NC) { stage(c + 1); asm volatile("cp.async.wait_group 1;" ::: "memory"); }
        else            { asm volatile("cp.async.wait_group 0;" ::: "memory"); }
        __syncthreads();
        const float* As = (const float*)(smem + (c & 1) * ABYTES);
        const float* Bs = (const float*)(smem + 2 * ABYTES + (c & 1) * ABYTES);
        #pragma unroll
        for (int ks = 0; ks < 4; ++ks) {
            const int kk = ks * 8 + t;
            uint32_t af[4][4], bf[4][2];
            #pragma unroll
            for (int mf = 0; mf < 4; ++mf) {
                const float* ap = As + (wm * 64 + mf * 16 + g) * SMS + kk;
                af[mf][0] = __float_as_uint(ap[0]);
                af[mf][1] = __float_as_uint(ap[8 * SMS]);
                af[mf][2] = __float_as_uint(ap[4]);
                af[mf][3] = __float_as_uint(ap[8 * SMS + 4]);
            }
            #pragma unroll
            for (int nf = 0; nf < 4; ++nf) {
                const float* bp = Bs + (wn * 32 + nf * 8 + g) * SMS + kk;
                bf[nf][0] = __float_as_uint(bp[0]);
                bf[nf][1] = __float_as_uint(bp[4]);
            }
            #pragma unroll
            for (int mf = 0; mf < 4; ++mf)
                #pragma unroll
                for (int nf = 0; nf < 4; ++nf)
                    mma_tf32(acc[mf][nf], af[mf], bf[nf]);
        }
        __syncthreads();
    }

    float* ush = (float*)smem;          // uw cache [8][512] + combined bias [512]
    if (EPI == 2) {
        for (int i = tid; i < 4096; i += 256) ush[i] = uw[i];
        for (int i = tid; i < 512; i += 256) ush[4096 + i] = bias[i] + ub[i];
        __syncthreads();
    }

    #pragma unroll
    for (int mf = 0; mf < 4; ++mf) {
        size_t row0 = (size_t)(cRow + wm * 64 + mf * 16 + g);
        size_t row1 = row0 + 8;
        float p0[8], p1[8];
        if (EPI == 2) {
            float4 a0 = *reinterpret_cast<const float4*>(cpre + row0 * 8);
            float4 a1 = *reinterpret_cast<const float4*>(cpre + row0 * 8 + 4);
            float4 b0 = *reinterpret_cast<const float4*>(cpre + row1 * 8);
            float4 b1 = *reinterpret_cast<const float4*>(cpre + row1 * 8 + 4);
            p0[0]=qgelu(a0.x); p0[1]=qgelu(a0.y); p0[2]=qgelu(a0.z); p0[3]=qgelu(a0.w);
            p0[4]=qgelu(a1.x); p0[5]=qgelu(a1.y); p0[6]=qgelu(a1.z); p0[7]=qgelu(a1.w);
            p1[0]=qgelu(b0.x); p1[1]=qgelu(b0.y); p1[2]=qgelu(b0.z); p1[3]=qgelu(b0.w);
            p1[4]=qgelu(b1.x); p1[5]=qgelu(b1.y); p1[6]=qgelu(b1.z); p1[7]=qgelu(b1.w);
        }
        #pragma unroll
        for (int nf = 0; nf < 4; ++nf) {
            int col = cCol + wn * 32 + nf * 8 + 2 * t;
            float v0 = acc[mf][nf][0], v1 = acc[mf][nf][1];
            float v2 = acc[mf][nf][2], v3 = acc[mf][nf][3];
            if (EPI == 2) {
                float u0 = ush[4096 + col], u1 = ush[4096 + col + 1];
                float u2 = u0, u3 = u1;
                #pragma unroll
                for (int a = 0; a < 8; ++a) {
                    float w0 = ush[a * 512 + col], w1 = ush[a * 512 + col + 1];
                    u0 += p0[a] * w0; u1 += p0[a] * w1;
                    u2 += p1[a] * w0; u3 += p1[a] * w1;
                }
                float2 r0 = *reinterpret_cast<const float2*>(&res[row0 * N + col]);
                float2 r1 = *reinterpret_cast<const float2*>(&res[row1 * N + col]);
                v0 += u0 + r0.x; v1 += u1 + r0.y;
                v2 += u2 + r1.x; v3 += u3 + r1.y;
            }
            *reinterpret_cast<float2*>(&C[row0 * N + col]) = make_float2(v0, v1);
            *reinterpret_cast<float2*>(&C[row1 * N + col]) = make_float2(v2, v3);
        }
    }
}

// ---------------- bf16 mma GEMM (ldmatrix fragments) ----------------
// EPI 2: +bias +gelu -> bf16 (ff1). EPI 3: +(bias+ub) +res +adapter_up -> f32 (ff2).
#define BSMS_E 72
#define BBYTES (128*BSMS_E*2)
template<int EPI>
__global__ __launch_bounds__(256, 2) void tc_gemm_bf16(const __nv_bfloat16* __restrict__ A,
                                                       const __nv_bfloat16* __restrict__ BT,
                                                       const float* __restrict__ bias,
                                                       void* __restrict__ Cv,
                                                       int M, int N, int K,
                                                       const float* __restrict__ res,
                                                       const float* __restrict__ cpre,
                                                       const float* __restrict__ uw,
                                                       const float* __restrict__ ub) {
    extern __shared__ char smem[];
    const uint32_t sb = smem_u32(smem);
    const int tid = threadIdx.x;
    const int lane = tid & 31;
    const int w = tid >> 5;
    const int wm = w & 1, wn = w >> 1;
    const int g = lane >> 2, t = lane & 3;
    const int cRow = blockIdx.y * 128;
    const int cCol = blockIdx.x * 128;
    const int r_st = tid >> 3;
    const int c_st = (tid & 7) << 3;

    // ldmatrix per-lane offsets (bytes)
    const uint32_t a_lane = ((uint32_t)(wm * 64 + (lane & 15)) * BSMS_E + (lane >> 4) * 8) * 2;
    const uint32_t b_lane = ((uint32_t)(wn * 32 + (lane & 7) + ((lane & 16) ? 8 : 0)) * BSMS_E
                             + ((lane & 8) ? 8 : 0)) * 2;

    float acc[4][4][4] = {};

    auto stage = [&](int kt) {
        const int k0 = kt << 6;
        const uint32_t ab = sb + (kt & 1) * BBYTES;
        const uint32_t bb = sb + 2 * BBYTES + (kt & 1) * BBYTES;
        #pragma unroll
        for (int i = 0; i < 4; ++i) {
            int r = r_st + i * 32;
            cp16(ab + (uint32_t)(r * BSMS_E + c_st) * 2, A + (size_t)(cRow + r) * K + k0 + c_st);
            cp16(bb + (uint32_t)(r * BSMS_E + c_st) * 2, BT + (size_t)(cCol + r) * K + k0 + c_st);
        }
        asm volatile("cp.async.commit_group;" ::: "memory");
    };

    const int NC = K >> 6;
    stage(0);
    for (int c = 0; c < NC; ++c) {
        if (c + 1 < NC) { stage(c + 1); asm volatile("cp.async.wait_group 1;" ::: "memory"); }
        else            { asm volatile("cp.async.wait_group 0;" ::: "memory"); }
        __syncthreads();
        const uint32_t As_u = sb + (c & 1) * BBYTES;
        const uint32_t Bs_u = sb + 2 * BBYTES + (c & 1) * BBYTES;
        #pragma unroll
        for (int ks = 0; ks < 4; ++ks) {
            uint32_t af[4][4], bf[4][2];
            #pragma unroll
            for (int mf = 0; mf < 4; ++mf)
                LDSM_X4(af[mf][0], af[mf][1], af[mf][2], af[mf][3],
                        As_u + a_lane + (uint32_t)(mf * 16 * BSMS_E + ks * 16) * 2);
            #pragma unroll
            for (int p = 0; p < 2; ++p) {
                uint32_t r0, r1, r2, r3;
                LDSM_X4(r0, r1, r2, r3,
                        Bs_u + b_lane + (uint32_t)(p * 16 * BSMS_E + ks * 16) * 2);
                bf[2 * p][0] = r0; bf[2 * p][1] = r1;
                bf[2 * p + 1][0] = r2; bf[2 * p + 1][1] = r3;
            }
            #pragma unroll
            for (int mf = 0; mf < 4; ++mf)
                #pragma unroll
                for (int nf = 0; nf < 4; ++nf)
                    mma_bf16(acc[mf][nf], af[mf], bf[nf]);
        }
        __syncthreads();
    }

    float* ush = (float*)smem;
    if (EPI == 3) {
        for (int i = tid; i < 4096; i += 256) ush[i] = uw[i];
        for (int i = tid; i < 512; i += 256) ush[4096 + i] = bias[i] + ub[i];
        __syncthreads();
    }

    #pragma unroll
    for (int mf = 0; mf < 4; ++mf) {
        size_t row0 = (size_t)(cRow + wm * 64 + mf * 16 + g);
        size_t row1 = row0 + 8;
        float p0[8], p1[8];
        if (EPI == 3) {
            float4 a0 = *reinterpret_cast<const float4*>(cpre + row0 * 8);
            float4 a1 = *reinterpret_cast<const float4*>(cpre + row0 * 8 + 4);
            float4 b0 = *reinterpret_cast<const float4*>(cpre + row1 * 8);
            float4 b1 = *reinterpret_cast<const float4*>(cpre + row1 * 8 + 4);
            p0[0]=qgelu(a0.x); p0[1]=qgelu(a0.y); p0[2]=qgelu(a0.z); p0[3]=qgelu(a0.w);
            p0[4]=qgelu(a1.x); p0[5]=qgelu(a1.y); p0[6]=qgelu(a1.z); p0[7]=qgelu(a1.w);
            p1[0]=qgelu(b0.x); p1[1]=qgelu(b0.y); p1[2]=qgelu(b0.z); p1[3]=qgelu(b0.w);
            p1[4]=qgelu(b1.x); p1[5]=qgelu(b1.y); p1[6]=qgelu(b1.z); p1[7]=qgelu(b1.w);
        }
        #pragma unroll
        for (int nf = 0; nf < 4; ++nf) {
            int col = cCol + wn * 32 + nf * 8 + 2 * t;
            if (EPI == 2) {
                float b0 = bias[col], b1 = bias[col + 1];
                uint32_t* C = (uint32_t*)Cv;
                *(C + (row0 * N + col) / 2) =
                    pack_bf16(gelu_exact(acc[mf][nf][0] + b0), gelu_exact(acc[mf][nf][1] + b1));
                *(C + (row1 * N + col) / 2) =
                    pack_bf16(gelu_exact(acc[mf][nf][2] + b0), gelu_exact(acc[mf][nf][3] + b1));
            } else {
                float u0 = ush[4096 + col], u1 = ush[4096 + col + 1];
                float u2 = u0, u3 = u1;
                #pragma unroll
                for (int a = 0; a < 8; ++a) {
                    float w0 = ush[a * 512 + col], w1 = ush[a * 512 + col + 1];
                    u0 += p0[a] * w0; u1 += p0[a] * w1;
                    u2 += p1[a] * w0; u3 += p1[a] * w1;
                }
                float2 r0 = *reinterpret_cast<const float2*>(&res[row0 * N + col]);
                float2 r1 = *reinterpret_cast<const float2*>(&res[row1 * N + col]);
                float* C = (float*)Cv;
                *reinterpret_cast<float2*>(&C[row0 * N + col]) =
                    make_float2(acc[mf][nf][0] + u0 + r0.x, acc[mf][nf][1] + u1 + r0.y);
                *reinterpret_cast<float2*>(&C[row1 * N + col]) =
                    make_float2(acc[mf][nf][2] + u2 + r1.x, acc[mf][nf][3] + u3 + r1.y);
            }
        }
    }
}

// ---------------- fused flash attention (tf32 mma) ----------------
#define FA_SMEM ((128*68 + 64*68 + 64*68) * 4)
__global__ __launch_bounds__(256) void flash_attn(const float* __restrict__ qkv,
                                                  float* __restrict__ O) {
    extern __shared__ float fs[];
    float* Ps = fs;
    float* Ks = fs + 128 * 68;
    float* Vt = Ks + 64 * 68;
    const int tid = threadIdx.x;
    const int lane = tid & 31;
    const int w = tid >> 5;
    const int g = lane >> 2, t = lane & 3;
    const int qt = blockIdx.x;
    const int bh = blockIdx.y;
    const int b = bh >> 3, h = bh & 7;
    const int r0 = w * 16 + g;

    const size_t qbase = ((size_t)b * NN + qt * 128) * 1536 + h * 64;
    #pragma unroll
    for (int i = 0; i < 8; ++i) {
        int lin = tid + 256 * i;
        int r = lin >> 4, c4 = (lin & 15) << 2;
        float4 q = *reinterpret_cast<const float4*>(qkv + qbase + (size_t)r * 1536 + c4);
        float* d = Ps + r * 68 + c4;
        d[0] = to_tf32(q.x * SCALE); d[1] = to_tf32(q.y * SCALE);
        d[2] = to_tf32(q.z * SCALE); d[3] = to_tf32(q.w * SCALE);
    }
    __syncthreads();
    uint32_t qf[8][4];
    #pragma unroll
    for (int ks = 0; ks < 8; ++ks) {
        const float* p = Ps + r0 * 68 + ks * 8 + t;
        qf[ks][0] = __float_as_uint(p[0]);
        qf[ks][1] = __float_as_uint(p[8 * 68]);
        qf[ks][2] = __float_as_uint(p[4]);
        qf[ks][3] = __float_as_uint(p[8 * 68 + 4]);
    }
    __syncthreads();

    float oacc[8][4] = {};
    float m0 = -1e30f, m1 = -1e30f, l0 = 0.f, l1 = 0.f;
    const size_t kbase = (size_t)b * NN * 1536 + 512 + h * 64;
    const size_t vbase = kbase + 512;

    for (int kt = 0; kt < 8; ++kt) {
        #pragma unroll
        for (int i = 0; i < 4; ++i) {
            int lin = tid + 256 * i;
            int r = lin >> 4, c4 = (lin & 15) << 2;
            size_t off = (size_t)(kt * 64 + r) * 1536 + c4;
            float4 kv = *reinterpret_cast<const float4*>(qkv + kbase + off);
            float* d = Ks + r * 68 + c4;
            d[0] = to_tf32(kv.x); d[1] = to_tf32(kv.y);
            d[2] = to_tf32(kv.z); d[3] = to_tf32(kv.w);
            float4 vv = *reinterpret_cast<const float4*>(qkv + vbase + off);
            Vt[(c4 + 0) * 68 + r] = to_tf32(vv.x);
            Vt[(c4 + 1) * 68 + r] = to_tf32(vv.y);
            Vt[(c4 + 2) * 68 + r] = to_tf32(vv.z);
            Vt[(c4 + 3) * 68 + r] = to_tf32(vv.w);
        }
        __syncthreads();

        float sacc[8][4] = {};
        #pragma unroll
        for (int ks = 0; ks < 8; ++ks) {
            #pragma unroll
            for (int nf = 0; nf < 8; ++nf) {
                const float* bp = Ks + (nf * 8 + g) * 68 + ks * 8 + t;
                uint32_t bfv[2] = {__float_as_uint(bp[0]), __float_as_uint(bp[4])};
                mma_tf32(sacc[nf], qf[ks], bfv);
            }
        }
        float mx0 = -1e30f, mx1 = -1e30f;
        #pragma unroll
        for (int nf = 0; nf < 8; ++nf) {
            mx0 = fmaxf(mx0, fmaxf(sacc[nf][0], sacc[nf][1]));
            mx1 = fmaxf(mx1, fmaxf(sacc[nf][2], sacc[nf][3]));
        }
        mx0 = fmaxf(mx0, __shfl_xor_sync(0xffffffffu, mx0, 1));
        mx0 = fmaxf(mx0, __shfl_xor_sync(0xffffffffu, mx0, 2));
        mx1 = fmaxf(mx1, __shfl_xor_sync(0xffffffffu, mx1, 1));
        mx1 = fmaxf(mx1, __shfl_xor_sync(0xffffffffu, mx1, 2));
        float mn0 = fmaxf(m0, mx0), mn1 = fmaxf(m1, mx1);
        float f0 = __expf(m0 - mn0), f1 = __expf(m1 - mn1);
        m0 = mn0; m1 = mn1;
        float rs0 = 0.f, rs1 = 0.f;
        #pragma unroll
        for (int nf = 0; nf < 8; ++nf) {
            sacc[nf][0] = __expf(sacc[nf][0] - mn0);
            sacc[nf][1] = __expf(sacc[nf][1] - mn0);
            sacc[nf][2] = __expf(sacc[nf][2] - mn1);
            sacc[nf][3] = __expf(sacc[nf][3] - mn1);
            rs0 += sacc[nf][0] + sacc[nf][1];
            rs1 += sacc[nf][2] + sacc[nf][3];
        }
        rs0 += __shfl_xor_sync(0xffffffffu, rs0, 1);
        rs0 += __shfl_xor_sync(0xffffffffu, rs0, 2);
        rs1 += __shfl_xor_sync(0xffffffffu, rs1, 1);
        rs1 += __shfl_xor_sync(0xffffffffu, rs1, 2);
        l0 = l0 * f0 + rs0; l1 = l1 * f1 + rs1;
        #pragma unroll
        for (int nf = 0; nf < 8; ++nf) {
            oacc[nf][0] *= f0; oacc[nf][1] *= f0;
            oacc[nf][2] *= f1; oacc[nf][3] *= f1;
        }
        #pragma unroll
        for (int nf = 0; nf < 8; ++nf) {
            float* pr = Ps + r0 * 68 + nf * 8 + 2 * t;
            *reinterpret_cast<float2*>(pr) =
                make_float2(to_tf32(sacc[nf][0]), to_tf32(sacc[nf][1]));
            *reinterpret_cast<float2*>(pr + 8 * 68) =
                make_float2(to_tf32(sacc[nf][2]), to_tf32(sacc[nf][3]));
        }
        __syncwarp();
        #pragma unroll
        for (int ks = 0; ks < 8; ++ks) {
            const float* ap = Ps + r0 * 68 + ks * 8 + t;
            uint32_t af[4] = {__float_as_uint(ap[0]), __float_as_uint(ap[8 * 68]),
                              __float_as_uint(ap[4]), __float_as_uint(ap[8 * 68 + 4])};
            #pragma unroll
            for (int nf = 0; nf < 8; ++nf) {
                const float* bp = Vt + (nf * 8 + g) * 68 + ks * 8 + t;
                uint32_t bfv[2] = {__float_as_uint(bp[0]), __float_as_uint(bp[4])};
                mma_tf32(oacc[nf], af, bfv);
            }
        }
        __syncthreads();
    }

    float i0 = 1.0f / l0, i1 = 1.0f / l1;
    size_t orow = (size_t)(b * NN + qt * 128 + r0);
    #pragma unroll
    for (int nf = 0; nf < 8; ++nf) {
        int col = h * 64 + nf * 8 + 2 * t;
        *reinterpret_cast<float2*>(&O[orow * CC + col]) =
            make_float2(to_tf32(oacc[nf][0] * i0), to_tf32(oacc[nf][1] * i0));
        *reinterpret_cast<float2*>(&O[(orow + 8) * CC + col]) =
            make_float2(to_tf32(oacc[nf][2] * i1), to_tf32(oacc[nf][3] * i1));
    }
}

// ---------------- adapter down ----------------
template<typename T>
__global__ __launch_bounds__(256) void down_kernel(const T* __restrict__ h,
                                                   const float* __restrict__ dw,
                                                   const float* __restrict__ db,
                                                   float* __restrict__ out) {
    __shared__ float wsh[512 * 8];
    for (int i = threadIdx.x; i < 4096; i += 256) wsh[i] = dw[i];
    __syncthreads();
    int warp = threadIdx.x >> 5, lane = threadIdx.x & 31;
    int row = blockIdx.x * 8 + warp;
    const T* hp = h + (size_t)row * CC;
    float acc[8] = {};
    for (int k = lane; k < 512; k += 32) {
        float xv = (float)hp[k];
        #pragma unroll
        for (int a = 0; a < 8; ++a) acc[a] += xv * wsh[k * 8 + a];
    }
    #pragma unroll
    for (int a = 0; a < 8; ++a) {
        #pragma unroll
        for (int o = 16; o > 0; o >>= 1)
            acc[a] += __shfl_down_sync(0xffffffffu, acc[a], o);
    }
    if (lane == 0) {
        #pragma unroll
        for (int a = 0; a < 8; ++a)
            out[(size_t)row * 8 + a] = qgelu(acc[a] + db[a]);
    }
}

// ---------------- tiny 3D conv ----------------
__global__ __launch_bounds__(256) void conv3d_kernel(const float* __restrict__ din,
                                                     const float* __restrict__ cw,
                                                     const float* __restrict__ cb,
                                                     float* __restrict__ out) {
    __shared__ float w[1728];
    __shared__ float bsh[8];
    for (int i = threadIdx.x; i < 1728; i += 256) w[i] = cw[i];
    if (threadIdx.x < 8) bsh[threadIdx.x] = cb[threadIdx.x];
    __syncthreads();
    int gid = blockIdx.x * 256 + threadIdx.x;
    int o  = gid & 7;
    int sp = (gid >> 3) & 511;
    int b  = gid >> 12;
    int xx = sp & 7, yy = (sp >> 3) & 7, zz = sp >> 6;
    float acc = bsh[o];
    for (int dz = -1; dz <= 1; ++dz) {
        int z = zz + dz; if ((unsigned)z > 7u) continue;
        for (int dy = -1; dy <= 1; ++dy) {
            int y = yy + dy; if ((unsigned)y > 7u) continue;
            for (int dx = -1; dx <= 1; ++dx) {
                int xc = xx + dx; if ((unsigned)xc > 7u) continue;
                const float* ip = din + ((size_t)b * 512 + z * 64 + y * 8 + xc) * 8;
                const float* wp = w + o * 216 + ((dz + 1) * 3 + (dy + 1)) * 3 + (dx + 1);
                #pragma unroll
                for (int i = 0; i < 8; ++i) acc += ip[i] * wp[i * 27];
            }
        }
    }
    out[gid] = acc;
}

// ---------------- launcher ----------------
static float* symaddr(const void* sym) {
    void* p = nullptr;
    cudaGetSymbolAddress(&p, sym);
    return (float*)p;
}

extern "C" void kernel_launch(void* const* d_in, const int* in_sizes, int n_in,
                              void* d_out, int out_size) {
    (void)in_sizes; (void)n_in; (void)out_size;
    const float* x      = (const float*)d_in[0];
    const float* pos    = (const float*)d_in[1];
    const float* ln1_g  = (const float*)d_in[2];
    const float* ln1_b  = (const float*)d_in[3];
    const float* qkv_w  = (const float*)d_in[4];
    const float* proj_w = (const float*)d_in[5];
    const float* proj_b = (const float*)d_in[6];
    const float* cp1_dw = (const float*)d_in[7];
    const float* cp1_db = (const float*)d_in[8];
    const float* cp1_cw = (const float*)d_in[9];
    const float* cp1_cb = (const float*)d_in[10];
    const float* cp1_uw = (const float*)d_in[11];
    const float* cp1_ub = (const float*)d_in[12];
    const float* ln2_g  = (const float*)d_in[13];
    const float* ln2_b  = (const float*)d_in[14];
    const float* ff_w1  = (const float*)d_in[15];
    const float* ff_b1  = (const float*)d_in[16];
    const float* ff_w2  = (const float*)d_in[17];
    const float* ff_b2  = (const float*)d_in[18];
    const float* cp2_dw = (const float*)d_in[19];
    const float* cp2_db = (const float*)d_in[20];
    const float* cp2_cw = (const float*)d_in[21];
    const float* cp2_cb = (const float*)d_in[22];
    const float* cp2_uw = (const float*)d_in[23];
    const float* cp2_ub = (const float*)d_in[24];
    float* out = (float*)d_out;

    float* bx    = symaddr(g_x);
    float* bh    = symaddr(g_h);
    __nv_bfloat16* bhb = (__nv_bfloat16*)symaddr(g_hb);
    float* bqkv  = symaddr(g_qkv);
    float* bao   = symaddr(g_ao);
    __nv_bfloat16* bmlpb = (__nv_bfloat16*)symaddr(g_mlpb);
    float* bd    = symaddr(g_d);
    float* bc    = symaddr(g_c);
    float* wqkvT = symaddr(g_wqkvT);
    float* wprojT= symaddr(g_wprojT);
    __nv_bfloat16* wff1T = (__nv_bfloat16*)symaddr(g_wff1T);
    __nv_bfloat16* wff2T = (__nv_bfloat16*)symaddr(g_wff2T);

    const int GEMM_SMEM = 4 * ABYTES;  // 73728
    cudaFuncSetAttribute(tc_gemm<0>, cudaFuncAttributeMaxDynamicSharedMemorySize, GEMM_SMEM);
    cudaFuncSetAttribute(tc_gemm<2>, cudaFuncAttributeMaxDynamicSharedMemorySize, GEMM_SMEM);
    cudaFuncSetAttribute(tc_gemm_bf16<2>, cudaFuncAttributeMaxDynamicSharedMemorySize, GEMM_SMEM);
    cudaFuncSetAttribute(tc_gemm_bf16<3>, cudaFuncAttributeMaxDynamicSharedMemorySize, GEMM_SMEM);
    cudaFuncSetAttribute(flash_attn, cudaFuncAttributeMaxDynamicSharedMemorySize, FA_SMEM);

    // weight transposes [K,N] -> [N,K]
    transpose_k<<<dim3(1536 / 32, 512 / 32), dim3(32, 8)>>>(qkv_w, wqkvT, 512, 1536);
    transpose_k<<<dim3(512 / 32, 512 / 32), dim3(32, 8)>>>(proj_w, wprojT, 512, 512);
    transpose_k_bf16<<<dim3(4096 / 32, 512 / 32), dim3(32, 8)>>>(ff_w1, wff1T, 512, 4096);
    transpose_k_bf16<<<dim3(512 / 32, 4096 / 32), dim3(32, 8)>>>(ff_w2, wff2T, 4096, 512);

    // x = x + pos ; h = LN1(x)
    add_ln<<<MROWS, 256>>>(x, pos, ln1_g, ln1_b, bx, bh);

    // convpass 1 (down + conv from h) — needed by proj epilogue
    down_kernel<float><<<MROWS / 8, 256>>>(bh, cp1_dw, cp1_db, bd);
    conv3d_kernel<<<MROWS * ADIM / 256, 256>>>(bd, cp1_cw, cp1_cb, bc);

    // qkv = h @ qkv_w (tf32)
    tc_gemm<0><<<dim3(12, 128), 256, GEMM_SMEM>>>(bh, wqkvT, nullptr, bqkv,
                                                  MROWS, 3 * CC, CC,
                                                  nullptr, nullptr, nullptr, nullptr);
    // fused attention
    flash_attn<<<dim3(4, BB * HH), 256, FA_SMEM>>>(bqkv, bao);

    // proj (tf32) fused: x = x + (ao@projW + proj_b) + up1(qgelu(conv1)) + cp1_ub
    tc_gemm<2><<<dim3(4, 128), 256, GEMM_SMEM>>>(bao, wprojT, proj_b, bx,
                                                 MROWS, CC, CC,
                                                 bx, bc, cp1_uw, cp1_ub);

    // h2 = LN2(x) -> bf16
    ln_bf16<<<MROWS, 256>>>(bx, ln2_g, ln2_b, bhb);

    // convpass 2 (down + conv from h2) — needed by ff2 epilogue
    down_kernel<__nv_bfloat16><<<MROWS / 8, 256>>>(bhb, cp2_dw, cp2_db, bd);
    conv3d_kernel<<<MROWS * ADIM / 256, 256>>>(bd, cp2_cw, cp2_cb, bc);

    // FFN (bf16 mma, ldmatrix)
    tc_gemm_bf16<2><<<dim3(32, 128), 256, GEMM_SMEM>>>(bhb, wff1T, ff_b1, bmlpb,
                                                       MROWS, MLPD, CC,
                                                       nullptr, nullptr, nullptr, nullptr);
    // ff2 fused: out = x + (mlp@w2 + ff_b2) + up2(qgelu(conv2)) + cp2_ub
    tc_gemm_bf16<3><<<dim3(4, 128), 256, GEMM_SMEM>>>(bmlpb, wff2T, ff_b2, out,
                                                      MROWS, CC, MLPD,
                                                      bx, bc, cp2_uw, cp2_ub);
}

// round 8
// speedup vs baseline: 5.7786x; 1.2941x over previous
#include <cuda_runtime.h>
#include <cuda_fp16.h>
#include <cstdint>

// ---------------- problem constants ----------------
#define BB    32
#define NN    512
#define CC    512
#define HH    8
#define DHD   64
#define ADIM  8
#define MLPD  4096
#define MROWS (BB*NN)          // 16384

// ---------------- static device scratch ----------------
__device__ __align__(16) float  g_x  [(size_t)MROWS*CC];
__device__ __align__(16) __half g_h  [(size_t)MROWS*CC];     // LN1 out
__device__ __align__(16) __half g_hb [(size_t)MROWS*CC];     // LN2 out
__device__ __align__(16) __half g_qkv[(size_t)MROWS*3*CC];
__device__ __align__(16) __half g_ao [(size_t)MROWS*CC];
__device__ __align__(16) __half g_mlp[(size_t)MROWS*MLPD];
__device__ __align__(16) float  g_d  [(size_t)MROWS*ADIM];
__device__ __align__(16) float  g_c  [(size_t)MROWS*ADIM];
// transposed fp16 weights [N,K]
__device__ __align__(16) __half g_wqkvT[(size_t)3*CC*CC];
__device__ __align__(16) __half g_wprojT[(size_t)CC*CC];
__device__ __align__(16) __half g_wff1T[(size_t)MLPD*CC];
__device__ __align__(16) __half g_wff2T[(size_t)CC*MLPD];

// ---------------- helpers ----------------
__device__ __forceinline__ float qgelu(float v) { return v / (1.0f + __expf(-1.702f * v)); }
__device__ __forceinline__ float gelu_exact(float v) { return 0.5f * v * (1.0f + erff(v * 0.70710678118654752f)); }
__device__ __forceinline__ uint32_t smem_u32(const void* p) {
    uint32_t a;
    asm("{ .reg .u64 t; cvta.to.shared.u64 t, %1; cvt.u32.u64 %0, t; }" : "=r"(a) : "l"(p));
    return a;
}
__device__ __forceinline__ void cp16(uint32_t saddr, const void* g) {
    asm volatile("cp.async.cg.shared.global [%0], [%1], 16;" :: "r"(saddr), "l"(g));
}
__device__ __forceinline__ void mma_fp16(float d[4], const uint32_t a[4], const uint32_t b[2]) {
    asm volatile("mma.sync.aligned.m16n8k16.row.col.f32.f16.f16.f32 "
        "{%0,%1,%2,%3}, {%4,%5,%6,%7}, {%8,%9}, {%0,%1,%2,%3};"
        : "+f"(d[0]), "+f"(d[1]), "+f"(d[2]), "+f"(d[3])
        : "r"(a[0]), "r"(a[1]), "r"(a[2]), "r"(a[3]), "r"(b[0]), "r"(b[1]));
}
#define LDSM_X4(r0, r1, r2, r3, addr) \
    asm volatile("ldmatrix.sync.aligned.m8n8.x4.shared.b16 {%0,%1,%2,%3}, [%4];" \
        : "=r"(r0), "=r"(r1), "=r"(r2), "=r"(r3) : "r"(addr))
#define LDSM_X4_T(r0, r1, r2, r3, addr) \
    asm volatile("ldmatrix.sync.aligned.m8n8.x4.trans.shared.b16 {%0,%1,%2,%3}, [%4];" \
        : "=r"(r0), "=r"(r1), "=r"(r2), "=r"(r3) : "r"(addr))
__device__ __forceinline__ uint32_t pack_half(float a, float b) {
    __half2 v = __floats2half2_rn(a, b);
    return *reinterpret_cast<uint32_t*>(&v);
}

__device__ __forceinline__ float blockReduceSum256(float v) {
    __shared__ float sh[8];
    int lane = threadIdx.x & 31, w = threadIdx.x >> 5;
    #pragma unroll
    for (int o = 16; o > 0; o >>= 1) v += __shfl_down_sync(0xffffffffu, v, o);
    if (lane == 0) sh[w] = v;
    __syncthreads();
    if (threadIdx.x < 8) {
        float t = sh[threadIdx.x];
        t += __shfl_down_sync(0xffu, t, 4);
        t += __shfl_down_sync(0xffu, t, 2);
        t += __shfl_down_sync(0xffu, t, 1);
        if (threadIdx.x == 0) sh[0] = t;
    }
    __syncthreads();
    float r = sh[0];
    __syncthreads();
    return r;
}

// ---------------- fused (x+pos) + LN1 -> fp16 ----------------
__global__ __launch_bounds__(256) void add_ln(const float* __restrict__ xin,
                                              const float* __restrict__ pos,
                                              const float* __restrict__ g,
                                              const float* __restrict__ b,
                                              float* __restrict__ xout,
                                              __half* __restrict__ hout) {
    size_t row = blockIdx.x;
    int tid = threadIdx.x;
    float v0 = xin[row * CC + tid]       + pos[row * CC + tid];
    float v1 = xin[row * CC + tid + 256] + pos[row * CC + tid + 256];
    xout[row * CC + tid]       = v0;
    xout[row * CC + tid + 256] = v1;
    float mean = blockReduceSum256(v0 + v1) * (1.0f / 512.0f);
    float d0 = v0 - mean, d1 = v1 - mean;
    float var = blockReduceSum256(d0 * d0 + d1 * d1) * (1.0f / 512.0f);
    float inv = rsqrtf(var + 1e-5f);
    hout[row * CC + tid]       = __float2half_rn(d0 * inv * g[tid]       + b[tid]);
    hout[row * CC + tid + 256] = __float2half_rn(d1 * inv * g[tid + 256] + b[tid + 256]);
}

// ---------------- LN2 (f32 in -> fp16 out) ----------------
__global__ __launch_bounds__(256) void ln_h(const float* __restrict__ in,
                                            const float* __restrict__ g,
                                            const float* __restrict__ b,
                                            __half* __restrict__ out) {
    size_t row = blockIdx.x;
    int tid = threadIdx.x;
    float v0 = in[row * CC + tid], v1 = in[row * CC + tid + 256];
    float mean = blockReduceSum256(v0 + v1) * (1.0f / 512.0f);
    float d0 = v0 - mean, d1 = v1 - mean;
    float var = blockReduceSum256(d0 * d0 + d1 * d1) * (1.0f / 512.0f);
    float inv = rsqrtf(var + 1e-5f);
    out[row * CC + tid]       = __float2half_rn(d0 * inv * g[tid]       + b[tid]);
    out[row * CC + tid + 256] = __float2half_rn(d1 * inv * g[tid + 256] + b[tid + 256]);
}

// ---------------- transpose (f32 in, fp16 out) ----------------
__global__ void transpose_k_h(const float* __restrict__ in, __half* __restrict__ out,
                              int R, int Cc) {
    __shared__ float t[32][33];
    int bx = blockIdx.x * 32, by = blockIdx.y * 32;
    #pragma unroll
    for (int i = 0; i < 32; i += 8)
        t[threadIdx.y + i][threadIdx.x] = in[(size_t)(by + threadIdx.y + i) * Cc + bx + threadIdx.x];
    __syncthreads();
    #pragma unroll
    for (int i = 0; i < 32; i += 8)
        out[(size_t)(bx + threadIdx.y + i) * R + by + threadIdx.x] =
            __float2half_rn(t[threadIdx.x][threadIdx.y + i]);
}

// ---------------- fp16 mma GEMM: C[M,N] = A[M,K] @ BT[N,K]^T ----------------
// EPI 0: plain -> fp16 (qkv). EPI 1: +bias +gelu -> fp16 (ff1).
// EPI 2: +(bias+ub) +res +adapter_up -> f32 (proj, ff2).
#define SME 72
#define TBYTES (128*SME*2)   // 18432
template<int EPI>
__global__ __launch_bounds__(256, 2) void tc_gemm16(const __half* __restrict__ A,
                                                    const __half* __restrict__ BT,
                                                    const float* __restrict__ bias,
                                                    void* __restrict__ Cv,
                                                    int M, int N, int K,
                                                    const float* __restrict__ res,
                                                    const float* __restrict__ cpre,
                                                    const float* __restrict__ uw,
                                                    const float* __restrict__ ub) {
    extern __shared__ char smem[];
    const uint32_t sb = smem_u32(smem);
    const int tid = threadIdx.x;
    const int lane = tid & 31;
    const int w = tid >> 5;
    const int wm = w & 1, wn = w >> 1;
    const int g = lane >> 2, t = lane & 3;
    const int cRow = blockIdx.y * 128;
    const int cCol = blockIdx.x * 128;
    const int r_st = tid >> 3;
    const int c_st = (tid & 7) << 3;

    const uint32_t a_lane = ((uint32_t)(wm * 64 + (lane & 15)) * SME + (lane >> 4) * 8) * 2;
    const uint32_t b_lane = ((uint32_t)(wn * 32 + (lane & 7) + ((lane & 16) ? 8 : 0)) * SME
                             + ((lane & 8) ? 8 : 0)) * 2;

    float acc[4][4][4] = {};

    auto stage = [&](int kt) {
        const int k0 = kt << 6;
        const uint32_t ab = sb + (kt & 1) * TBYTES;
        const uint32_t bb = sb + 2 * TBYTES + (kt & 1) * TBYTES;
        #pragma unroll
        for (int i = 0; i < 4; ++i) {
            int r = r_st + i * 32;
            cp16(ab + (uint32_t)(r * SME + c_st) * 2, A + (size_t)(cRow + r) * K + k0 + c_st);
            cp16(bb + (uint32_t)(r * SME + c_st) * 2, BT + (size_t)(cCol + r) * K + k0 + c_st);
        }
        asm volatile("cp.async.commit_group;" ::: "memory");
    };

    const int NC = K >> 6;
    stage(0);
    for (int c = 0; c < NC; ++c) {
        if (c + 1 < NC) { stage(c + 1); asm volatile("cp.async.wait_group 1;" ::: "memory"); }
        else            { asm volatile("cp.async.wait_group 0;" ::: "memory"); }
        __syncthreads();
        const uint32_t As_u = sb + (c & 1) * TBYTES;
        const uint32_t Bs_u = sb + 2 * TBYTES + (c & 1) * TBYTES;
        #pragma unroll
        for (int ks = 0; ks < 4; ++ks) {
            uint32_t af[4][4], bf[4][2];
            #pragma unroll
            for (int mf = 0; mf < 4; ++mf)
                LDSM_X4(af[mf][0], af[mf][1], af[mf][2], af[mf][3],
                        As_u + a_lane + (uint32_t)(mf * 16 * SME + ks * 16) * 2);
            #pragma unroll
            for (int p = 0; p < 2; ++p) {
                uint32_t r0, r1, r2, r3;
                LDSM_X4(r0, r1, r2, r3,
                        Bs_u + b_lane + (uint32_t)(p * 16 * SME + ks * 16) * 2);
                bf[2 * p][0] = r0; bf[2 * p][1] = r1;
                bf[2 * p + 1][0] = r2; bf[2 * p + 1][1] = r3;
            }
            #pragma unroll
            for (int mf = 0; mf < 4; ++mf)
                #pragma unroll
                for (int nf = 0; nf < 4; ++nf)
                    mma_fp16(acc[mf][nf], af[mf], bf[nf]);
        }
        __syncthreads();
    }

    float* ush = (float*)smem;
    if (EPI == 2) {
        for (int i = tid; i < 4096; i += 256) ush[i] = uw[i];
        for (int i = tid; i < 512; i += 256) ush[4096 + i] = bias[i] + ub[i];
        __syncthreads();
    }

    #pragma unroll
    for (int mf = 0; mf < 4; ++mf) {
        size_t row0 = (size_t)(cRow + wm * 64 + mf * 16 + g);
        size_t row1 = row0 + 8;
        float p0[8], p1[8];
        if (EPI == 2) {
            float4 a0 = *reinterpret_cast<const float4*>(cpre + row0 * 8);
            float4 a1 = *reinterpret_cast<const float4*>(cpre + row0 * 8 + 4);
            float4 b0 = *reinterpret_cast<const float4*>(cpre + row1 * 8);
            float4 b1 = *reinterpret_cast<const float4*>(cpre + row1 * 8 + 4);
            p0[0]=qgelu(a0.x); p0[1]=qgelu(a0.y); p0[2]=qgelu(a0.z); p0[3]=qgelu(a0.w);
            p0[4]=qgelu(a1.x); p0[5]=qgelu(a1.y); p0[6]=qgelu(a1.z); p0[7]=qgelu(a1.w);
            p1[0]=qgelu(b0.x); p1[1]=qgelu(b0.y); p1[2]=qgelu(b0.z); p1[3]=qgelu(b0.w);
            p1[4]=qgelu(b1.x); p1[5]=qgelu(b1.y); p1[6]=qgelu(b1.z); p1[7]=qgelu(b1.w);
        }
        #pragma unroll
        for (int nf = 0; nf < 4; ++nf) {
            int col = cCol + wn * 32 + nf * 8 + 2 * t;
            if (EPI == 0) {
                uint32_t* C = (uint32_t*)Cv;
                C[(row0 * N + col) >> 1] = pack_half(acc[mf][nf][0], acc[mf][nf][1]);
                C[(row1 * N + col) >> 1] = pack_half(acc[mf][nf][2], acc[mf][nf][3]);
            } else if (EPI == 1) {
                float b0 = bias[col], b1 = bias[col + 1];
                uint32_t* C = (uint32_t*)Cv;
                C[(row0 * N + col) >> 1] =
                    pack_half(gelu_exact(acc[mf][nf][0] + b0), gelu_exact(acc[mf][nf][1] + b1));
                C[(row1 * N + col) >> 1] =
                    pack_half(gelu_exact(acc[mf][nf][2] + b0), gelu_exact(acc[mf][nf][3] + b1));
            } else {
                float u0 = ush[4096 + col], u1 = ush[4096 + col + 1];
                float u2 = u0, u3 = u1;
                #pragma unroll
                for (int a = 0; a < 8; ++a) {
                    float w0 = ush[a * 512 + col], w1 = ush[a * 512 + col + 1];
                    u0 += p0[a] * w0; u1 += p0[a] * w1;
                    u2 += p1[a] * w0; u3 += p1[a] * w1;
                }
                float2 r0 = *reinterpret_cast<const float2*>(&res[row0 * N + col]);
                float2 r1 = *reinterpret_cast<const float2*>(&res[row1 * N + col]);
                float* C = (float*)Cv;
                *reinterpret_cast<float2*>(&C[row0 * N + col]) =
                    make_float2(acc[mf][nf][0] + u0 + r0.x, acc[mf][nf][1] + u1 + r0.y);
                *reinterpret_cast<float2*>(&C[row1 * N + col]) =
                    make_float2(acc[mf][nf][2] + u2 + r1.x, acc[mf][nf][3] + u3 + r1.y);
            }
        }
    }
}

// ---------------- fused flash attention (fp16 mma, P in registers) ----------------
#define FH 72
__global__ __launch_bounds__(256) void flash_attn_h(const __half* __restrict__ qkv,
                                                    __half* __restrict__ O) {
    __shared__ __half fb[128 * FH];           // 18432 B; Q phase, then K|V
    const int tid = threadIdx.x;
    const int lane = tid & 31;
    const int w = tid >> 5;
    const int g = lane >> 2, t = lane & 3;
    const int qt = blockIdx.x;
    const int bhid = blockIdx.y;
    const int b = bhid >> 3, h = bhid & 7;
    const int r0 = w * 16 + g;

    // stage Q * SCALE (exact: *2^-3) into fb   [FIXED: 1024 iters, 8-half stride]
    const __half* qptr = qkv + ((size_t)b * NN + qt * 128) * 1536 + h * 64;
    const __half2 sc = __floats2half2_rn(0.125f, 0.125f);
    #pragma unroll
    for (int i = 0; i < 4; ++i) {
        int idx = tid + 256 * i;              // 0..1023
        int r = idx >> 3, q = (idx & 7) * 8;  // 128 rows x 64 halves
        uint4 v = *reinterpret_cast<const uint4*>(qptr + (size_t)r * 1536 + q);
        __half2* pv = reinterpret_cast<__half2*>(&v);
        pv[0] = __hmul2(pv[0], sc); pv[1] = __hmul2(pv[1], sc);
        pv[2] = __hmul2(pv[2], sc); pv[3] = __hmul2(pv[3], sc);
        *reinterpret_cast<uint4*>(fb + r * FH + q) = v;
    }
    __syncthreads();
    uint32_t qf[4][4];
    {
        const uint32_t* Q2 = reinterpret_cast<const uint32_t*>(fb);
        #pragma unroll
        for (int ks = 0; ks < 4; ++ks) {
            int base = r0 * (FH / 2) + ks * 8 + t;
            qf[ks][0] = Q2[base];
            qf[ks][1] = Q2[base + 8 * (FH / 2)];
            qf[ks][2] = Q2[base + 4];
            qf[ks][3] = Q2[base + 8 * (FH / 2) + 4];
        }
    }
    __syncthreads();

    __half* Ks = fb;
    __half* Vs = fb + 64 * FH;
    const uint32_t vs_u = smem_u32(Vs);
    const __half* kptr = qkv + (size_t)b * NN * 1536 + 512 + h * 64;
    const __half* vptr = kptr + 512;

    float oacc[8][4] = {};
    float m0 = -1e30f, m1 = -1e30f, l0 = 0.f, l1 = 0.f;

    for (int kt = 0; kt < 8; ++kt) {
        #pragma unroll
        for (int i = 0; i < 2; ++i) {
            int idx = tid + 256 * i;          // 0..511
            int r = idx >> 3, q = (idx & 7) * 8;
            size_t off = (size_t)(kt * 64 + r) * 1536 + q;
            *reinterpret_cast<uint4*>(Ks + r * FH + q) =
                *reinterpret_cast<const uint4*>(kptr + off);
            *reinterpret_cast<uint4*>(Vs + r * FH + q) =
                *reinterpret_cast<const uint4*>(vptr + off);
        }
        __syncthreads();

        // S = Q K^T
        float sacc[8][4] = {};
        const uint32_t* K2 = reinterpret_cast<const uint32_t*>(Ks);
        #pragma unroll
        for (int ks = 0; ks < 4; ++ks) {
            #pragma unroll
            for (int nf = 0; nf < 8; ++nf) {
                int base = (nf * 8 + g) * (FH / 2) + ks * 8 + t;
                uint32_t bfv[2] = {K2[base], K2[base + 4]};
                mma_fp16(sacc[nf], qf[ks], bfv);
            }
        }
        // online softmax
        float mx0 = -1e30f, mx1 = -1e30f;
        #pragma unroll
        for (int nf = 0; nf < 8; ++nf) {
            mx0 = fmaxf(mx0, fmaxf(sacc[nf][0], sacc[nf][1]));
            mx1 = fmaxf(mx1, fmaxf(sacc[nf][2], sacc[nf][3]));
        }
        mx0 = fmaxf(mx0, __shfl_xor_sync(0xffffffffu, mx0, 1));
        mx0 = fmaxf(mx0, __shfl_xor_sync(0xffffffffu, mx0, 2));
        mx1 = fmaxf(mx1, __shfl_xor_sync(0xffffffffu, mx1, 1));
        mx1 = fmaxf(mx1, __shfl_xor_sync(0xffffffffu, mx1, 2));
        float mn0 = fmaxf(m0, mx0), mn1 = fmaxf(m1, mx1);
        float f0 = __expf(m0 - mn0), f1 = __expf(m1 - mn1);
        m0 = mn0; m1 = mn1;
        float rs0 = 0.f, rs1 = 0.f;
        #pragma unroll
        for (int nf = 0; nf < 8; ++nf) {
            sacc[nf][0] = __expf(sacc[nf][0] - mn0);
            sacc[nf][1] = __expf(sacc[nf][1] - mn0);
            sacc[nf][2] = __expf(sacc[nf][2] - mn1);
            sacc[nf][3] = __expf(sacc[nf][3] - mn1);
            rs0 += sacc[nf][0] + sacc[nf][1];
            rs1 += sacc[nf][2] + sacc[nf][3];
        }
        rs0 += __shfl_xor_sync(0xffffffffu, rs0, 1);
        rs0 += __shfl_xor_sync(0xffffffffu, rs0, 2);
        rs1 += __shfl_xor_sync(0xffffffffu, rs1, 1);
        rs1 += __shfl_xor_sync(0xffffffffu, rs1, 2);
        l0 = l0 * f0 + rs0; l1 = l1 * f1 + rs1;
        #pragma unroll
        for (int nf = 0; nf < 8; ++nf) {
            oacc[nf][0] *= f0; oacc[nf][1] *= f0;
            oacc[nf][2] *= f1; oacc[nf][3] *= f1;
        }
        // O += P @ V  (P fragments built in registers from sacc)
        #pragma unroll
        for (int ks = 0; ks < 4; ++ks) {
            uint32_t af[4] = {
                pack_half(sacc[2 * ks][0],     sacc[2 * ks][1]),
                pack_half(sacc[2 * ks][2],     sacc[2 * ks][3]),
                pack_half(sacc[2 * ks + 1][0], sacc[2 * ks + 1][1]),
                pack_half(sacc[2 * ks + 1][2], sacc[2 * ks + 1][3])};
            #pragma unroll
            for (int p = 0; p < 4; ++p) {
                uint32_t r0v, r1v, r2v, r3v;
                uint32_t addr = vs_u +
                    ((uint32_t)((16 * ks + (lane & 7) + ((lane & 8) ? 8 : 0)) * FH
                                + p * 16 + ((lane & 16) ? 8 : 0)) << 1);
                LDSM_X4_T(r0v, r1v, r2v, r3v, addr);
                uint32_t b0[2] = {r0v, r1v}, b1[2] = {r2v, r3v};
                mma_fp16(oacc[2 * p],     af, b0);
                mma_fp16(oacc[2 * p + 1], af, b1);
            }
        }
        __syncthreads();
    }

    float i0 = 1.0f / l0, i1 = 1.0f / l1;
    size_t orow = (size_t)(b * NN + qt * 128 + r0);
    uint32_t* O2 = reinterpret_cast<uint32_t*>(O);
    #pragma unroll
    for (int nf = 0; nf < 8; ++nf) {
        int col = h * 64 + nf * 8 + 2 * t;
        O2[(orow * CC + col) >> 1]       = pack_half(oacc[nf][0] * i0, oacc[nf][1] * i0);
        O2[((orow + 8) * CC + col) >> 1] = pack_half(oacc[nf][2] * i1, oacc[nf][3] * i1);
    }
}

// ---------------- adapter down ----------------
__global__ __launch_bounds__(256) void down_kernel(const __half* __restrict__ h,
                                                   const float* __restrict__ dw,
                                                   const float* __restrict__ db,
                                                   float* __restrict__ out) {
    __shared__ float wsh[512 * 8];
    for (int i = threadIdx.x; i < 4096; i += 256) wsh[i] = dw[i];
    __syncthreads();
    int warp = threadIdx.x >> 5, lane = threadIdx.x & 31;
    int row = blockIdx.x * 8 + warp;
    const __half* hp = h + (size_t)row * CC;
    float acc[8] = {};
    for (int k = lane; k < 512; k += 32) {
        float xv = __half2float(hp[k]);
        #pragma unroll
        for (int a = 0; a < 8; ++a) acc[a] += xv * wsh[k * 8 + a];
    }
    #pragma unroll
    for (int a = 0; a < 8; ++a) {
        #pragma unroll
        for (int o = 16; o > 0; o >>= 1)
            acc[a] += __shfl_down_sync(0xffffffffu, acc[a], o);
    }
    if (lane == 0) {
        #pragma unroll
        for (int a = 0; a < 8; ++a)
            out[(size_t)row * 8 + a] = qgelu(acc[a] + db[a]);
    }
}

// ---------------- tiny 3D conv ----------------
__global__ __launch_bounds__(256) void conv3d_kernel(const float* __restrict__ din,
                                                     const float* __restrict__ cw,
                                                     const float* __restrict__ cb,
                                                     float* __restrict__ out) {
    __shared__ float w[1728];
    __shared__ float bsh[8];
    for (int i = threadIdx.x; i < 1728; i += 256) w[i] = cw[i];
    if (threadIdx.x < 8) bsh[threadIdx.x] = cb[threadIdx.x];
    __syncthreads();
    int gid = blockIdx.x * 256 + threadIdx.x;
    int o  = gid & 7;
    int sp = (gid >> 3) & 511;
    int b  = gid >> 12;
    int xx = sp & 7, yy = (sp >> 3) & 7, zz = sp >> 6;
    float acc = bsh[o];
    for (int dz = -1; dz <= 1; ++dz) {
        int z = zz + dz; if ((unsigned)z > 7u) continue;
        for (int dy = -1; dy <= 1; ++dy) {
            int y = yy + dy; if ((unsigned)y > 7u) continue;
            for (int dx = -1; dx <= 1; ++dx) {
                int xc = xx + dx; if ((unsigned)xc > 7u) continue;
                const float* ip = din + ((size_t)b * 512 + z * 64 + y * 8 + xc) * 8;
                const float* wp = w + o * 216 + ((dz + 1) * 3 + (dy + 1)) * 3 + (dx + 1);
                #pragma unroll
                for (int i = 0; i < 8; ++i) acc += ip[i] * wp[i * 27];
            }
        }
    }
    out[gid] = acc;
}

// ---------------- launcher ----------------
static float* symaddr(const void* sym) {
    void* p = nullptr;
    cudaGetSymbolAddress(&p, sym);
    return (float*)p;
}

extern "C" void kernel_launch(void* const* d_in, const int* in_sizes, int n_in,
                              void* d_out, int out_size) {
    (void)in_sizes; (void)n_in; (void)out_size;
    const float* x      = (const float*)d_in[0];
    const float* pos    = (const float*)d_in[1];
    const float* ln1_g  = (const float*)d_in[2];
    const float* ln1_b  = (const float*)d_in[3];
    const float* qkv_w  = (const float*)d_in[4];
    const float* proj_w = (const float*)d_in[5];
    const float* proj_b = (const float*)d_in[6];
    const float* cp1_dw = (const float*)d_in[7];
    const float* cp1_db = (const float*)d_in[8];
    const float* cp1_cw = (const float*)d_in[9];
    const float* cp1_cb = (const float*)d_in[10];
    const float* cp1_uw = (const float*)d_in[11];
    const float* cp1_ub = (const float*)d_in[12];
    const float* ln2_g  = (const float*)d_in[13];
    const float* ln2_b  = (const float*)d_in[14];
    const float* ff_w1  = (const float*)d_in[15];
    const float* ff_b1  = (const float*)d_in[16];
    const float* ff_w2  = (const float*)d_in[17];
    const float* ff_b2  = (const float*)d_in[18];
    const float* cp2_dw = (const float*)d_in[19];
    const float* cp2_db = (const float*)d_in[20];
    const float* cp2_cw = (const float*)d_in[21];
    const float* cp2_cb = (const float*)d_in[22];
    const float* cp2_uw = (const float*)d_in[23];
    const float* cp2_ub = (const float*)d_in[24];
    float* out = (float*)d_out;

    float*  bx    = symaddr(g_x);
    __half* bh    = (__half*)symaddr(g_h);
    __half* bhb   = (__half*)symaddr(g_hb);
    __half* bqkv  = (__half*)symaddr(g_qkv);
    __half* bao   = (__half*)symaddr(g_ao);
    __half* bmlp  = (__half*)symaddr(g_mlp);
    float*  bd    = symaddr(g_d);
    float*  bc    = symaddr(g_c);
    __half* wqkvT = (__half*)symaddr(g_wqkvT);
    __half* wprojT= (__half*)symaddr(g_wprojT);
    __half* wff1T = (__half*)symaddr(g_wff1T);
    __half* wff2T = (__half*)symaddr(g_wff2T);

    const int GEMM_SMEM = 4 * TBYTES;  // 73728
    cudaFuncSetAttribute(tc_gemm16<0>, cudaFuncAttributeMaxDynamicSharedMemorySize, GEMM_SMEM);
    cudaFuncSetAttribute(tc_gemm16<1>, cudaFuncAttributeMaxDynamicSharedMemorySize, GEMM_SMEM);
    cudaFuncSetAttribute(tc_gemm16<2>, cudaFuncAttributeMaxDynamicSharedMemorySize, GEMM_SMEM);

    // weight transposes [K,N] -> [N,K] fp16
    transpose_k_h<<<dim3(1536 / 32, 512 / 32), dim3(32, 8)>>>(qkv_w, wqkvT, 512, 1536);
    transpose_k_h<<<dim3(512 / 32, 512 / 32), dim3(32, 8)>>>(proj_w, wprojT, 512, 512);
    transpose_k_h<<<dim3(4096 / 32, 512 / 32), dim3(32, 8)>>>(ff_w1, wff1T, 512, 4096);
    transpose_k_h<<<dim3(512 / 32, 4096 / 32), dim3(32, 8)>>>(ff_w2, wff2T, 4096, 512);

    // x = x + pos ; h = LN1(x) -> fp16
    add_ln<<<MROWS, 256>>>(x, pos, ln1_g, ln1_b, bx, bh);

    // convpass 1 (needed by proj epilogue)
    down_kernel<<<MROWS / 8, 256>>>(bh, cp1_dw, cp1_db, bd);
    conv3d_kernel<<<MROWS * ADIM / 256, 256>>>(bd, cp1_cw, cp1_cb, bc);

    // qkv = h @ qkv_w -> fp16
    tc_gemm16<0><<<dim3(12, 128), 256, GEMM_SMEM>>>(bh, wqkvT, nullptr, bqkv,
                                                    MROWS, 3 * CC, CC,
                                                    nullptr, nullptr, nullptr, nullptr);
    // fused fp16 flash attention -> fp16
    flash_attn_h<<<dim3(4, BB * HH), 256>>>(bqkv, bao);

    // proj fused: x = x + (ao@projW + proj_b) + up1(qgelu(conv1)) + cp1_ub
    tc_gemm16<2><<<dim3(4, 128), 256, GEMM_SMEM>>>(bao, wprojT, proj_b, bx,
                                                   MROWS, CC, CC,
                                                   bx, bc, cp1_uw, cp1_ub);

    // h2 = LN2(x) -> fp16
    ln_h<<<MROWS, 256>>>(bx, ln2_g, ln2_b, bhb);

    // convpass 2 (needed by ff2 epilogue)
    down_kernel<<<MROWS / 8, 256>>>(bhb, cp2_dw, cp2_db, bd);
    conv3d_kernel<<<MROWS * ADIM / 256, 256>>>(bd, cp2_cw, cp2_cb, bc);

    // FFN fp16
    tc_gemm16<1><<<dim3(32, 128), 256, GEMM_SMEM>>>(bhb, wff1T, ff_b1, bmlp,
                                                    MROWS, MLPD, CC,
                                                    nullptr, nullptr, nullptr, nullptr);
    tc_gemm16<2><<<dim3(4, 128), 256, GEMM_SMEM>>>(bmlp, wff2T, ff_b2, out,
                                                   MROWS, CC, MLPD,
                                                   bx, bc, cp2_uw, cp2_ub);
}